// round 4
// baseline (speedup 1.0000x reference)
#include <cuda_runtime.h>
#include <cuda_bf16.h>
#include <cstdint>

#define NE 600000
#define NN 50000
#define DIM 128
#define TM 64
#define NTHREADS 256
#define NSM 152       // GB300: 152 SMs (persistent loops tolerate any actual count)
#define LDA 132       // padded row stride for A/H tiles (floats)
#define LDW 130       // padded row stride for transposed weights (floats)

// Scratch for node projections (device globals: no runtime allocation allowed).
__device__ float g_sproj[(size_t)NN * DIM];
__device__ float g_dproj[(size_t)NN * DIM];

struct SmemT {
    float W1T[DIM * LDW];  // transposed weight 1: W1T[k*LDW + j] = W1[j][k]
    float W2T[DIM * LDW];  // transposed weight 2
    float A[TM * LDA];     // input tile (row-major, padded)
    float H[TM * LDA];     // hidden tile
    int srcIdx[TM];
    int dstIdx[TM];
};

__device__ __forceinline__ void pack_dup(unsigned long long& d, float a) {
    unsigned u = __float_as_uint(a);
    asm("mov.b64 %0, {%1, %1};" : "=l"(d) : "r"(u));
}
__device__ __forceinline__ float2 unpack2(unsigned long long v) {
    unsigned lo, hi;
    asm("mov.b64 {%0, %1}, %2;" : "=r"(lo), "=r"(hi) : "l"(v));
    return make_float2(__uint_as_float(lo), __uint_as_float(hi));
}
__device__ __forceinline__ void ffma2(unsigned long long& acc,
                                      unsigned long long a, unsigned long long b) {
    asm("fma.rn.f32x2 %0, %1, %2, %0;" : "+l"(acc) : "l"(a), "l"(b));
}

// Load 128x128 row-major weight W[j][k] into SMEM transposed: WT[k][j].
__device__ __forceinline__ void load_weight_T(float* WT, const float* __restrict__ W, int t) {
    for (int p = t; p < DIM * (DIM / 4); p += NTHREADS) {
        int j = p >> 5;         // output row of W
        int c4 = p & 31;        // group of 4 k's
        float4 v = reinterpret_cast<const float4*>(W)[p];
        int k = c4 * 4;
        WT[(k + 0) * LDW + j] = v.x;
        WT[(k + 1) * LDW + j] = v.y;
        WT[(k + 2) * LDW + j] = v.z;
        WT[(k + 3) * LDW + j] = v.w;
    }
}

// Register-tiled GEMM using packed f32x2 FMA.
// Each thread: rows ty*4..ty*4+3, column pairs (2*tx + 32*j, +1), j=0..3.
// acc[i][j] is a packed float2 accumulator.
__device__ __forceinline__ void gemm_tile_x2(
    const float* __restrict__ A, const float* __restrict__ WT,
    int tx, int ty, unsigned long long acc[4][4])
{
    #pragma unroll 4
    for (int k = 0; k < DIM; k += 2) {
        float2 av[4];
        #pragma unroll
        for (int i = 0; i < 4; i++)
            av[i] = *reinterpret_cast<const float2*>(&A[(ty * 4 + i) * LDA + k]);
        unsigned long long pa0[4], pa1[4];
        #pragma unroll
        for (int i = 0; i < 4; i++) {
            pack_dup(pa0[i], av[i].x);
            pack_dup(pa1[i], av[i].y);
        }
        unsigned long long pb0[4], pb1[4];
        #pragma unroll
        for (int j = 0; j < 4; j++) {
            pb0[j] = *reinterpret_cast<const unsigned long long*>(
                &WT[(k + 0) * LDW + 2 * tx + 32 * j]);
            pb1[j] = *reinterpret_cast<const unsigned long long*>(
                &WT[(k + 1) * LDW + 2 * tx + 32 * j]);
        }
        #pragma unroll
        for (int i = 0; i < 4; i++) {
            #pragma unroll
            for (int j = 0; j < 4; j++) {
                ffma2(acc[i][j], pa0[i], pb0[j]);
                ffma2(acc[i][j], pa1[i], pb1[j]);
            }
        }
    }
}

// ---------------- Node projection kernel ----------------
// sproj = nfeat @ W_s^T, dproj = nfeat @ W_d^T  (no bias).
__global__ void __launch_bounds__(NTHREADS, 1)
node_kernel(const float* __restrict__ nfeat,
            const float* __restrict__ W_s, const float* __restrict__ W_d)
{
    extern __shared__ char smem_raw[];
    SmemT& sm = *reinterpret_cast<SmemT*>(smem_raw);
    const int t = threadIdx.x;
    const int tx = t & 15, ty = t >> 4;

    load_weight_T(sm.W1T, W_s, t);
    load_weight_T(sm.W2T, W_d, t);

    const int ntiles = (NN + TM - 1) / TM;
    for (int tile = blockIdx.x; tile < ntiles; tile += gridDim.x) {
        const int n0 = tile * TM;
        __syncthreads();
        for (int p = t; p < TM * (DIM / 4); p += NTHREADS) {
            int r = p >> 5, c4 = p & 31;
            float4 v = make_float4(0.f, 0.f, 0.f, 0.f);
            if (n0 + r < NN)
                v = reinterpret_cast<const float4*>(nfeat)[(size_t)(n0 + r) * 32 + c4];
            *reinterpret_cast<float4*>(&sm.A[r * LDA + c4 * 4]) = v;
        }
        __syncthreads();

        unsigned long long acc[4][4];
        #pragma unroll
        for (int i = 0; i < 4; i++)
            #pragma unroll
            for (int j = 0; j < 4; j++) acc[i][j] = 0ull;
        gemm_tile_x2(sm.A, sm.W1T, tx, ty, acc);
        #pragma unroll
        for (int i = 0; i < 4; i++) {
            int n = n0 + ty * 4 + i;
            if (n < NN) {
                #pragma unroll
                for (int j = 0; j < 4; j++) {
                    float2 p = unpack2(acc[i][j]);
                    *reinterpret_cast<float2*>(&g_sproj[(size_t)n * DIM + 2 * tx + 32 * j]) = p;
                }
            }
        }

        #pragma unroll
        for (int i = 0; i < 4; i++)
            #pragma unroll
            for (int j = 0; j < 4; j++) acc[i][j] = 0ull;
        gemm_tile_x2(sm.A, sm.W2T, tx, ty, acc);
        #pragma unroll
        for (int i = 0; i < 4; i++) {
            int n = n0 + ty * 4 + i;
            if (n < NN) {
                #pragma unroll
                for (int j = 0; j < 4; j++) {
                    float2 p = unpack2(acc[i][j]);
                    *reinterpret_cast<float2*>(&g_dproj[(size_t)n * DIM + 2 * tx + 32 * j]) = p;
                }
            }
        }
    }
}

// ---------------- Fused edge kernel ----------------
__global__ void __launch_bounds__(NTHREADS, 1)
edge_kernel(const float* __restrict__ efeat,
            const int* __restrict__ src, const int* __restrict__ dst,
            const float* __restrict__ W_e, const float* __restrict__ b1,
            const float* __restrict__ W_o, const float* __restrict__ b_o,
            const float* __restrict__ gamma, const float* __restrict__ beta,
            float* __restrict__ out)
{
    extern __shared__ char smem_raw[];
    SmemT& sm = *reinterpret_cast<SmemT*>(smem_raw);
    const int t = threadIdx.x;
    const int tx = t & 15, ty = t >> 4;

    load_weight_T(sm.W1T, W_e, t);
    load_weight_T(sm.W2T, W_o, t);

    float rb1[4][2], rbo[4][2], rg[4][2], rbt[4][2];
    #pragma unroll
    for (int j = 0; j < 4; j++) {
        int c = 2 * tx + 32 * j;
        rb1[j][0] = b1[c];    rb1[j][1] = b1[c + 1];
        rbo[j][0] = b_o[c];   rbo[j][1] = b_o[c + 1];
        rg[j][0]  = gamma[c]; rg[j][1]  = gamma[c + 1];
        rbt[j][0] = beta[c];  rbt[j][1] = beta[c + 1];
    }

    const int ntiles = NE / TM;  // 9375 exactly
    for (int tile = blockIdx.x; tile < ntiles; tile += gridDim.x) {
        const int e0 = tile * TM;
        __syncthreads();  // protect A/H reuse from previous iteration's readers
        for (int p = t; p < TM * (DIM / 4); p += NTHREADS) {
            int r = p >> 5, c4 = p & 31;
            float4 v = reinterpret_cast<const float4*>(efeat)[(size_t)(e0 + r) * 32 + c4];
            *reinterpret_cast<float4*>(&sm.A[r * LDA + c4 * 4]) = v;
        }
        if (t < TM) {
            sm.srcIdx[t] = src[e0 + t];
            sm.dstIdx[t] = dst[e0 + t];
        }
        __syncthreads();

        // Gather prefetch (independent of GEMM1; loads overlap the FMA stream).
        float2 gsum[4][4];
        #pragma unroll
        for (int i = 0; i < 4; i++) {
            const float* sp = g_sproj + (size_t)sm.srcIdx[ty * 4 + i] * DIM;
            const float* dp = g_dproj + (size_t)sm.dstIdx[ty * 4 + i] * DIM;
            #pragma unroll
            for (int j = 0; j < 4; j++) {
                float2 s = *reinterpret_cast<const float2*>(&sp[2 * tx + 32 * j]);
                float2 d = *reinterpret_cast<const float2*>(&dp[2 * tx + 32 * j]);
                gsum[i][j] = make_float2(s.x + d.x, s.y + d.y);
            }
        }

        unsigned long long acc[4][4];
        #pragma unroll
        for (int i = 0; i < 4; i++)
            #pragma unroll
            for (int j = 0; j < 4; j++) acc[i][j] = 0ull;
        gemm_tile_x2(sm.A, sm.W1T, tx, ty, acc);

        // bias + gathers + SiLU -> H
        #pragma unroll
        for (int i = 0; i < 4; i++) {
            int r = ty * 4 + i;
            #pragma unroll
            for (int j = 0; j < 4; j++) {
                float2 v = unpack2(acc[i][j]);
                float x0 = v.x + rb1[j][0] + gsum[i][j].x;
                float x1 = v.y + rb1[j][1] + gsum[i][j].y;
                float s0 = x0 / (1.0f + __expf(-x0));
                float s1 = x1 / (1.0f + __expf(-x1));
                *reinterpret_cast<float2*>(&sm.H[r * LDA + 2 * tx + 32 * j]) =
                    make_float2(s0, s1);
            }
        }
        __syncthreads();

        #pragma unroll
        for (int i = 0; i < 4; i++)
            #pragma unroll
            for (int j = 0; j < 4; j++) acc[i][j] = 0ull;
        gemm_tile_x2(sm.H, sm.W2T, tx, ty, acc);

        // + b_o, LayerNorm (row = 16 lanes), affine, + efeat residual, store
        #pragma unroll
        for (int i = 0; i < 4; i++) {
            int r = ty * 4 + i;
            float v[4][2];
            float sum = 0.f, sq = 0.f;
            #pragma unroll
            for (int j = 0; j < 4; j++) {
                float2 p = unpack2(acc[i][j]);
                v[j][0] = p.x + rbo[j][0];
                v[j][1] = p.y + rbo[j][1];
                sum += v[j][0] + v[j][1];
                sq  += v[j][0] * v[j][0] + v[j][1] * v[j][1];
            }
            #pragma unroll
            for (int d = 1; d < 16; d <<= 1) {
                sum += __shfl_xor_sync(0xffffffffu, sum, d);
                sq  += __shfl_xor_sync(0xffffffffu, sq, d);
            }
            float mean = sum * (1.0f / 128.0f);
            float var  = sq * (1.0f / 128.0f) - mean * mean;
            float rstd = rsqrtf(var + 1e-5f);
            size_t ebase = (size_t)(e0 + r) * DIM;
            #pragma unroll
            for (int j = 0; j < 4; j++) {
                int c = 2 * tx + 32 * j;
                float2 res = *reinterpret_cast<const float2*>(&sm.A[r * LDA + c]);
                float o0 = (v[j][0] - mean) * rstd * rg[j][0] + rbt[j][0] + res.x;
                float o1 = (v[j][1] - mean) * rstd * rg[j][1] + rbt[j][1] + res.y;
                *reinterpret_cast<float2*>(&out[ebase + c]) = make_float2(o0, o1);
            }
        }
    }
}

extern "C" void kernel_launch(void* const* d_in, const int* in_sizes, int n_in,
                              void* d_out, int out_size) {
    const float* efeat = (const float*)d_in[0];
    const float* nfeat = (const float*)d_in[1];
    const int*   src   = (const int*)d_in[2];
    const int*   dst   = (const int*)d_in[3];
    const float* W_e   = (const float*)d_in[4];
    const float* W_s   = (const float*)d_in[5];
    const float* W_d   = (const float*)d_in[6];
    const float* b1    = (const float*)d_in[7];
    const float* W_o   = (const float*)d_in[8];
    const float* b_o   = (const float*)d_in[9];
    const float* gamma = (const float*)d_in[10];
    const float* beta  = (const float*)d_in[11];
    float* out = (float*)d_out;

    int smem = (int)sizeof(SmemT);
    cudaFuncSetAttribute(node_kernel, cudaFuncAttributeMaxDynamicSharedMemorySize, smem);
    cudaFuncSetAttribute(edge_kernel, cudaFuncAttributeMaxDynamicSharedMemorySize, smem);

    node_kernel<<<NSM, NTHREADS, smem>>>(nfeat, W_s, W_d);
    edge_kernel<<<NSM, NTHREADS, smem>>>(efeat, src, dst, W_e, b1, W_o, b_o,
                                         gamma, beta, out);
    // nfeat passthrough -> second output
    cudaMemcpyAsync(out + (size_t)NE * DIM, nfeat,
                    (size_t)NN * DIM * sizeof(float), cudaMemcpyDeviceToDevice);
}

// round 8
// speedup vs baseline: 1.1249x; 1.1249x over previous
#include <cuda_runtime.h>
#include <cuda_bf16.h>
#include <cstdint>

#define NE 600000
#define NN 50000
#define DIM 128
#define NTHREADS 256
#define NSM 152

// Scratch for node projections
__device__ float g_sproj[(size_t)NN * DIM];
__device__ float g_dproj[(size_t)NN * DIM];

// ---------------- common helpers ----------------
__device__ __forceinline__ uint32_t smem_u32(const void* p) {
    uint32_t a;
    asm("{ .reg .u64 t; cvta.to.shared.u64 t, %1; cvt.u32.u64 %0, t; }" : "=r"(a) : "l"(p));
    return a;
}

// Swizzled tile layout: 128 rows x 128 bf16, row stride 256B.
// 16B chunk index c (0..15) -> (c&8) | ((c ^ r) & 7): ldmatrix conflict-free.
__device__ __forceinline__ uint32_t swz(int r, int kb) {
    int chunk = kb >> 4;
    int c2 = (chunk & 8) | ((chunk ^ r) & 7);
    return (uint32_t)(r * 256 + c2 * 16 + (kb & 15));
}

__device__ __forceinline__ void split_bf16(float x, __nv_bfloat16& h, __nv_bfloat16& l) {
    h = __float2bfloat16_rn(x);
    l = __float2bfloat16_rn(x - __bfloat162float(h));
}

// load 128x128 fp32 row-major matrix, split into hi/lo bf16 swizzled tiles
__device__ __forceinline__ void load_split_matrix(char* hiB, char* loB,
                                                  const float* __restrict__ W, int t) {
    for (int p = t; p < DIM * (DIM / 4); p += NTHREADS) {
        int r = p >> 5, c4 = p & 31;
        float4 v = reinterpret_cast<const float4*>(W)[p];
        __nv_bfloat16 h0, l0, h1, l1, h2, l2, h3, l3;
        split_bf16(v.x, h0, l0); split_bf16(v.y, h1, l1);
        split_bf16(v.z, h2, l2); split_bf16(v.w, h3, l3);
        uint32_t o = swz(r, c4 * 8);
        *reinterpret_cast<__nv_bfloat162*>(hiB + o)     = __nv_bfloat162(h0, h1);
        *reinterpret_cast<__nv_bfloat162*>(hiB + o + 4) = __nv_bfloat162(h2, h3);
        *reinterpret_cast<__nv_bfloat162*>(loB + o)     = __nv_bfloat162(l0, l1);
        *reinterpret_cast<__nv_bfloat162*>(loB + o + 4) = __nv_bfloat162(l2, l3);
    }
}

__device__ __forceinline__ void ldsm4(uint32_t addr, uint32_t r[4]) {
    asm volatile("ldmatrix.sync.aligned.m8n8.x4.shared.b16 {%0,%1,%2,%3}, [%4];"
                 : "=r"(r[0]), "=r"(r[1]), "=r"(r[2]), "=r"(r[3]) : "r"(addr));
}
__device__ __forceinline__ void mma16816(float c[4], const uint32_t a[4],
                                         uint32_t b0, uint32_t b1) {
    asm volatile("mma.sync.aligned.m16n8k16.row.col.f32.bf16.bf16.f32 "
                 "{%0,%1,%2,%3}, {%4,%5,%6,%7}, {%8,%9}, {%0,%1,%2,%3};"
                 : "+f"(c[0]), "+f"(c[1]), "+f"(c[2]), "+f"(c[3])
                 : "r"(a[0]), "r"(a[1]), "r"(a[2]), "r"(a[3]), "r"(b0), "r"(b1));
}

// Warp GEMM: D(M32xN64) = A(M32xK128) * W^T(K128xN64), 3-term bf16 split.
// A tiles at aHi/aLo, W (NxK row-major) tiles at wHi/wLo. acc zeroed inside.
__device__ __forceinline__ void warp_gemm_split(
    uint32_t aHi, uint32_t aLo, uint32_t wHi, uint32_t wLo,
    int wm, int wn, int lane, float acc[2][8][4])
{
    #pragma unroll
    for (int mt = 0; mt < 2; mt++)
        #pragma unroll
        for (int n8 = 0; n8 < 8; n8++)
            #pragma unroll
            for (int c = 0; c < 4; c++) acc[mt][n8][c] = 0.f;

    int arow[2];
    #pragma unroll
    for (int mt = 0; mt < 2; mt++)
        arow[mt] = wm * 32 + mt * 16 + ((lane >> 3) & 1) * 8 + (lane & 7);
    const int akhi = (lane >> 4) * 8;
    int brow[4];
    #pragma unroll
    for (int np = 0; np < 4; np++)
        brow[np] = wn * 64 + np * 16 + (lane >> 4) * 8 + (lane & 7);
    const int bkhi = ((lane >> 3) & 1) * 8;

    #pragma unroll
    for (int ks = 0; ks < 8; ks++) {
        const int k0 = ks * 16;
        uint32_t ah[2][4], al[2][4];
        #pragma unroll
        for (int mt = 0; mt < 2; mt++) {
            uint32_t o = swz(arow[mt], (k0 + akhi) * 2);
            ldsm4(aHi + o, ah[mt]);
            ldsm4(aLo + o, al[mt]);
        }
        #pragma unroll
        for (int np = 0; np < 4; np++) {
            uint32_t bo = swz(brow[np], (k0 + bkhi) * 2);
            uint32_t bh[4], bl[4];
            ldsm4(wHi + bo, bh);
            #pragma unroll
            for (int mt = 0; mt < 2; mt++) {
                mma16816(acc[mt][2 * np],     ah[mt], bh[0], bh[1]);
                mma16816(acc[mt][2 * np + 1], ah[mt], bh[2], bh[3]);
                mma16816(acc[mt][2 * np],     al[mt], bh[0], bh[1]);
                mma16816(acc[mt][2 * np + 1], al[mt], bh[2], bh[3]);
            }
            ldsm4(wLo + bo, bl);
            #pragma unroll
            for (int mt = 0; mt < 2; mt++) {
                mma16816(acc[mt][2 * np],     ah[mt], bl[0], bl[1]);
                mma16816(acc[mt][2 * np + 1], ah[mt], bl[2], bl[3]);
            }
        }
    }
}

// ================= SIMT node kernel (unchanged, proven) =================
#define TMN 64
#define LDA 132
#define LDW 130
struct SmemT {
    float W1T[DIM * LDW];
    float W2T[DIM * LDW];
    float A[TMN * LDA];
    float H[TMN * LDA];
};
__device__ __forceinline__ void pack_dup(unsigned long long& d, float a) {
    unsigned u = __float_as_uint(a);
    asm("mov.b64 %0, {%1, %1};" : "=l"(d) : "r"(u));
}
__device__ __forceinline__ float2 unpack2(unsigned long long v) {
    unsigned lo, hi;
    asm("mov.b64 {%0, %1}, %2;" : "=r"(lo), "=r"(hi) : "l"(v));
    return make_float2(__uint_as_float(lo), __uint_as_float(hi));
}
__device__ __forceinline__ void ffma2(unsigned long long& acc,
                                      unsigned long long a, unsigned long long b) {
    asm("fma.rn.f32x2 %0, %1, %2, %0;" : "+l"(acc) : "l"(a), "l"(b));
}
__device__ __forceinline__ void load_weight_T(float* WT, const float* __restrict__ W, int t) {
    for (int p = t; p < DIM * (DIM / 4); p += NTHREADS) {
        int j = p >> 5, c4 = p & 31;
        float4 v = reinterpret_cast<const float4*>(W)[p];
        int k = c4 * 4;
        WT[(k + 0) * LDW + j] = v.x; WT[(k + 1) * LDW + j] = v.y;
        WT[(k + 2) * LDW + j] = v.z; WT[(k + 3) * LDW + j] = v.w;
    }
}
__device__ __forceinline__ void gemm_tile_x2(const float* __restrict__ A,
                                             const float* __restrict__ WT,
                                             int tx, int ty, unsigned long long acc[4][4]) {
    #pragma unroll 4
    for (int k = 0; k < DIM; k += 2) {
        float2 av[4];
        #pragma unroll
        for (int i = 0; i < 4; i++)
            av[i] = *reinterpret_cast<const float2*>(&A[(ty * 4 + i) * LDA + k]);
        unsigned long long pa0[4], pa1[4];
        #pragma unroll
        for (int i = 0; i < 4; i++) { pack_dup(pa0[i], av[i].x); pack_dup(pa1[i], av[i].y); }
        unsigned long long pb0[4], pb1[4];
        #pragma unroll
        for (int j = 0; j < 4; j++) {
            pb0[j] = *reinterpret_cast<const unsigned long long*>(&WT[(k + 0) * LDW + 2 * tx + 32 * j]);
            pb1[j] = *reinterpret_cast<const unsigned long long*>(&WT[(k + 1) * LDW + 2 * tx + 32 * j]);
        }
        #pragma unroll
        for (int i = 0; i < 4; i++)
            #pragma unroll
            for (int j = 0; j < 4; j++) { ffma2(acc[i][j], pa0[i], pb0[j]); ffma2(acc[i][j], pa1[i], pb1[j]); }
    }
}
__global__ void __launch_bounds__(NTHREADS, 1)
node_kernel(const float* __restrict__ nfeat,
            const float* __restrict__ W_s, const float* __restrict__ W_d)
{
    extern __shared__ char smem_raw[];
    SmemT& sm = *reinterpret_cast<SmemT*>(smem_raw);
    const int t = threadIdx.x;
    const int tx = t & 15, ty = t >> 4;
    load_weight_T(sm.W1T, W_s, t);
    load_weight_T(sm.W2T, W_d, t);
    const int ntiles = (NN + TMN - 1) / TMN;
    for (int tile = blockIdx.x; tile < ntiles; tile += gridDim.x) {
        const int n0 = tile * TMN;
        __syncthreads();
        for (int p = t; p < TMN * (DIM / 4); p += NTHREADS) {
            int r = p >> 5, c4 = p & 31;
            float4 v = make_float4(0.f, 0.f, 0.f, 0.f);
            if (n0 + r < NN)
                v = reinterpret_cast<const float4*>(nfeat)[(size_t)(n0 + r) * 32 + c4];
            *reinterpret_cast<float4*>(&sm.A[r * LDA + c4 * 4]) = v;
        }
        __syncthreads();
        unsigned long long acc[4][4];
        #pragma unroll
        for (int i = 0; i < 4; i++)
            #pragma unroll
            for (int j = 0; j < 4; j++) acc[i][j] = 0ull;
        gemm_tile_x2(sm.A, sm.W1T, tx, ty, acc);
        #pragma unroll
        for (int i = 0; i < 4; i++) {
            int n = n0 + ty * 4 + i;
            if (n < NN)
                #pragma unroll
                for (int j = 0; j < 4; j++) {
                    float2 p = unpack2(acc[i][j]);
                    *reinterpret_cast<float2*>(&g_sproj[(size_t)n * DIM + 2 * tx + 32 * j]) = p;
                }
        }
        #pragma unroll
        for (int i = 0; i < 4; i++)
            #pragma unroll
            for (int j = 0; j < 4; j++) acc[i][j] = 0ull;
        gemm_tile_x2(sm.A, sm.W2T, tx, ty, acc);
        #pragma unroll
        for (int i = 0; i < 4; i++) {
            int n = n0 + ty * 4 + i;
            if (n < NN)
                #pragma unroll
                for (int j = 0; j < 4; j++) {
                    float2 p = unpack2(acc[i][j]);
                    *reinterpret_cast<float2*>(&g_dproj[(size_t)n * DIM + 2 * tx + 32 * j]) = p;
                }
        }
    }
}

// ================= mma.sync edge kernel =================
#define OFF_W1HI 0
#define OFF_W1LO 32768
#define OFF_W2HI 65536
#define OFF_W2LO 98304
#define OFF_AHI  131072
#define OFF_ALO  163840
#define OFF_B1   196608
#define OFF_BO   197120
#define OFF_GM   197632
#define OFF_BT   198144
#define OFF_RSUM 198656   // float[2][128]
#define OFF_RSQ  200704   // float[2][128] (1KB each, padded)
#define OFF_SRC  202752   // int[128]
#define OFF_DST  203264
#define EDGE_SMEM_BYTES (203776 + 1024)

#define NTILES_E ((NE + 127) / 128)

__global__ void __launch_bounds__(NTHREADS, 1)
edge_mma_kernel(const float* __restrict__ efeat,
                const int* __restrict__ src, const int* __restrict__ dst,
                const float* __restrict__ W_e, const float* __restrict__ b1,
                const float* __restrict__ W_o, const float* __restrict__ b_o,
                const float* __restrict__ gamma, const float* __restrict__ beta,
                float* __restrict__ out)
{
    extern __shared__ char smem_raw[];
    char* ab = (char*)(((uintptr_t)smem_raw + 1023) & ~(uintptr_t)1023);
    const int t = threadIdx.x;
    const int wid = t >> 5, lane = t & 31;
    const int wm = wid & 3, wn = wid >> 2;

    const uint32_t u_ahi = smem_u32(ab + OFF_AHI);
    const uint32_t u_alo = smem_u32(ab + OFF_ALO);
    const uint32_t u_w1h = smem_u32(ab + OFF_W1HI);
    const uint32_t u_w1l = smem_u32(ab + OFF_W1LO);
    const uint32_t u_w2h = smem_u32(ab + OFF_W2HI);
    const uint32_t u_w2l = smem_u32(ab + OFF_W2LO);

    float* b1s = (float*)(ab + OFF_B1);
    float* bos = (float*)(ab + OFF_BO);
    float* gms = (float*)(ab + OFF_GM);
    float* bts = (float*)(ab + OFF_BT);
    float* rsum = (float*)(ab + OFF_RSUM);
    float* rsq  = (float*)(ab + OFF_RSQ);
    int* srcS = (int*)(ab + OFF_SRC);
    int* dstS = (int*)(ab + OFF_DST);

    load_split_matrix(ab + OFF_W1HI, ab + OFF_W1LO, W_e, t);
    load_split_matrix(ab + OFF_W2HI, ab + OFF_W2LO, W_o, t);
    if (t < 128) { b1s[t] = b1[t]; bos[t] = b_o[t]; gms[t] = gamma[t]; bts[t] = beta[t]; }

    const int quad = lane >> 2, qt = lane & 3;

    for (int tile = blockIdx.x; tile < NTILES_E; tile += gridDim.x) {
        const int e0 = tile * 128;
        __syncthreads();  // previous tile fully consumed

        // ---- load + split efeat tile; load indices
        for (int p = t; p < DIM * 32; p += NTHREADS) {
            int r = p >> 5, c4 = p & 31;
            int e = e0 + r;
            float4 v = make_float4(0.f, 0.f, 0.f, 0.f);
            if (e < NE) v = reinterpret_cast<const float4*>(efeat)[(size_t)e * 32 + c4];
            __nv_bfloat16 h0, l0, h1, l1, h2, l2, h3, l3;
            split_bf16(v.x, h0, l0); split_bf16(v.y, h1, l1);
            split_bf16(v.z, h2, l2); split_bf16(v.w, h3, l3);
            uint32_t o = swz(r, c4 * 8);
            *reinterpret_cast<__nv_bfloat162*>(ab + OFF_AHI + o)     = __nv_bfloat162(h0, h1);
            *reinterpret_cast<__nv_bfloat162*>(ab + OFF_AHI + o + 4) = __nv_bfloat162(h2, h3);
            *reinterpret_cast<__nv_bfloat162*>(ab + OFF_ALO + o)     = __nv_bfloat162(l0, l1);
            *reinterpret_cast<__nv_bfloat162*>(ab + OFF_ALO + o + 4) = __nv_bfloat162(l2, l3);
        }
        if (t < 128) {
            int e = e0 + t;
            srcS[t] = (e < NE) ? src[e] : 0;
            dstS[t] = (e < NE) ? dst[e] : 0;
        }
        __syncthreads();

        // ---- GEMM1
        float acc[2][8][4];
        warp_gemm_split(u_ahi, u_alo, u_w1h, u_w1l, wm, wn, lane, acc);
        __syncthreads();  // all warps done reading A before H overwrite

        // ---- epilogue 1: + b1 + gathers, SiLU, split -> H into A buffers
        #pragma unroll
        for (int mt = 0; mt < 2; mt++) {
            #pragma unroll
            for (int rh = 0; rh < 2; rh++) {
                int row = wm * 32 + mt * 16 + quad + rh * 8;
                const float* sp = g_sproj + (size_t)srcS[row] * DIM;
                const float* dp = g_dproj + (size_t)dstS[row] * DIM;
                #pragma unroll
                for (int n8 = 0; n8 < 8; n8++) {
                    int col = wn * 64 + n8 * 8 + 2 * qt;
                    float2 s2 = *reinterpret_cast<const float2*>(&sp[col]);
                    float2 d2 = *reinterpret_cast<const float2*>(&dp[col]);
                    float2 b2 = *reinterpret_cast<const float2*>(&b1s[col]);
                    float x0 = acc[mt][n8][rh * 2 + 0] + b2.x + s2.x + d2.x;
                    float x1 = acc[mt][n8][rh * 2 + 1] + b2.y + s2.y + d2.y;
                    float v0 = x0 / (1.0f + __expf(-x0));
                    float v1 = x1 / (1.0f + __expf(-x1));
                    __nv_bfloat16 h0, l0, h1, l1;
                    split_bf16(v0, h0, l0); split_bf16(v1, h1, l1);
                    uint32_t o = swz(row, col * 2);
                    *reinterpret_cast<__nv_bfloat162*>(ab + OFF_AHI + o) = __nv_bfloat162(h0, h1);
                    *reinterpret_cast<__nv_bfloat162*>(ab + OFF_ALO + o) = __nv_bfloat162(l0, l1);
                }
            }
        }
        __syncthreads();

        // ---- GEMM2
        warp_gemm_split(u_ahi, u_alo, u_w2h, u_w2l, wm, wn, lane, acc);

        // ---- epilogue 2: + b_o, LayerNorm partials
        #pragma unroll
        for (int mt = 0; mt < 2; mt++) {
            #pragma unroll
            for (int rh = 0; rh < 2; rh++) {
                int row = wm * 32 + mt * 16 + quad + rh * 8;
                float s = 0.f, q = 0.f;
                #pragma unroll
                for (int n8 = 0; n8 < 8; n8++) {
                    int col = wn * 64 + n8 * 8 + 2 * qt;
                    float2 b2 = *reinterpret_cast<const float2*>(&bos[col]);
                    float v0 = acc[mt][n8][rh * 2 + 0] + b2.x;
                    float v1 = acc[mt][n8][rh * 2 + 1] + b2.y;
                    acc[mt][n8][rh * 2 + 0] = v0;
                    acc[mt][n8][rh * 2 + 1] = v1;
                    s += v0 + v1;
                    q += v0 * v0 + v1 * v1;
                }
                s += __shfl_xor_sync(0xffffffffu, s, 1);
                s += __shfl_xor_sync(0xffffffffu, s, 2);
                q += __shfl_xor_sync(0xffffffffu, q, 1);
                q += __shfl_xor_sync(0xffffffffu, q, 2);
                if (qt == 0) {
                    rsum[wn * 128 + row] = s;
                    rsq[wn * 128 + row] = q;
                }
            }
        }
        __syncthreads();

        // ---- normalize + affine + residual + store
        #pragma unroll
        for (int mt = 0; mt < 2; mt++) {
            #pragma unroll
            for (int rh = 0; rh < 2; rh++) {
                int row = wm * 32 + mt * 16 + quad + rh * 8;
                int e = e0 + row;
                if (e >= NE) continue;
                float ts = rsum[row] + rsum[128 + row];
                float tq = rsq[row] + rsq[128 + row];
                float mean = ts * (1.0f / 128.0f);
                float var = tq * (1.0f / 128.0f) - mean * mean;
                float rstd = rsqrtf(var + 1e-5f);
                #pragma unroll
                for (int n8 = 0; n8 < 8; n8++) {
                    int col = wn * 64 + n8 * 8 + 2 * qt;
                    float2 g2 = *reinterpret_cast<const float2*>(&gms[col]);
                    float2 t2 = *reinterpret_cast<const float2*>(&bts[col]);
                    float2 r2 = *reinterpret_cast<const float2*>(&efeat[(size_t)e * DIM + col]);
                    float o0 = (acc[mt][n8][rh * 2 + 0] - mean) * rstd * g2.x + t2.x + r2.x;
                    float o1 = (acc[mt][n8][rh * 2 + 1] - mean) * rstd * g2.y + t2.y + r2.y;
                    *reinterpret_cast<float2*>(&out[(size_t)e * DIM + col]) = make_float2(o0, o1);
                }
            }
        }
    }
}

extern "C" void kernel_launch(void* const* d_in, const int* in_sizes, int n_in,
                              void* d_out, int out_size) {
    const float* efeat = (const float*)d_in[0];
    const float* nfeat = (const float*)d_in[1];
    const int*   src   = (const int*)d_in[2];
    const int*   dst   = (const int*)d_in[3];
    const float* W_e   = (const float*)d_in[4];
    const float* W_s   = (const float*)d_in[5];
    const float* W_d   = (const float*)d_in[6];
    const float* b1    = (const float*)d_in[7];
    const float* W_o   = (const float*)d_in[8];
    const float* b_o   = (const float*)d_in[9];
    const float* gamma = (const float*)d_in[10];
    const float* beta  = (const float*)d_in[11];
    float* out = (float*)d_out;

    int smemN = (int)sizeof(SmemT);
    cudaFuncSetAttribute(node_kernel, cudaFuncAttributeMaxDynamicSharedMemorySize, smemN);
    cudaFuncSetAttribute(edge_mma_kernel, cudaFuncAttributeMaxDynamicSharedMemorySize,
                         EDGE_SMEM_BYTES);

    node_kernel<<<NSM, NTHREADS, smemN>>>(nfeat, W_s, W_d);
    edge_mma_kernel<<<NSM, NTHREADS, EDGE_SMEM_BYTES>>>(efeat, src, dst, W_e, b1, W_o, b_o,
                                                        gamma, beta, out);
    cudaMemcpyAsync(out + (size_t)NE * DIM, nfeat,
                    (size_t)NN * DIM * sizeof(float), cudaMemcpyDeviceToDevice);
}

// round 9
// speedup vs baseline: 1.5558x; 1.3831x over previous
#include <cuda_runtime.h>
#include <cuda_bf16.h>
#include <cstdint>

#define NE 600000
#define NN 50000
#define DIM 128
#define NTHREADS 256
#define ETHREADS 512
#define NSM 152

// Scratch for node projections
__device__ float g_sproj[(size_t)NN * DIM];
__device__ float g_dproj[(size_t)NN * DIM];

// ---------------- common helpers ----------------
__device__ __forceinline__ uint32_t smem_u32(const void* p) {
    uint32_t a;
    asm("{ .reg .u64 t; cvta.to.shared.u64 t, %1; cvt.u32.u64 %0, t; }" : "=r"(a) : "l"(p));
    return a;
}

// Swizzled tile layout: 128 rows x 128 bf16, row stride 256B.
// 16B chunk index c (0..15) -> (c&8) | ((c ^ r) & 7): ldmatrix conflict-free.
__device__ __forceinline__ uint32_t swz(int r, int kb) {
    int chunk = kb >> 4;
    int c2 = (chunk & 8) | ((chunk ^ r) & 7);
    return (uint32_t)(r * 256 + c2 * 16 + (kb & 15));
}

__device__ __forceinline__ void split_bf16(float x, __nv_bfloat16& h, __nv_bfloat16& l) {
    h = __float2bfloat16_rn(x);
    l = __float2bfloat16_rn(x - __bfloat162float(h));
}

// load 128x128 fp32 row-major matrix, split into hi/lo bf16 swizzled tiles
__device__ __forceinline__ void load_split_matrix(char* hiB, char* loB,
                                                  const float* __restrict__ W,
                                                  int t, int nthr) {
    for (int p = t; p < DIM * (DIM / 4); p += nthr) {
        int r = p >> 5, c4 = p & 31;
        float4 v = reinterpret_cast<const float4*>(W)[p];
        __nv_bfloat16 h0, l0, h1, l1, h2, l2, h3, l3;
        split_bf16(v.x, h0, l0); split_bf16(v.y, h1, l1);
        split_bf16(v.z, h2, l2); split_bf16(v.w, h3, l3);
        uint32_t o = swz(r, c4 * 8);
        *reinterpret_cast<__nv_bfloat162*>(hiB + o)     = __nv_bfloat162(h0, h1);
        *reinterpret_cast<__nv_bfloat162*>(hiB + o + 4) = __nv_bfloat162(h2, h3);
        *reinterpret_cast<__nv_bfloat162*>(loB + o)     = __nv_bfloat162(l0, l1);
        *reinterpret_cast<__nv_bfloat162*>(loB + o + 4) = __nv_bfloat162(l2, l3);
    }
}

__device__ __forceinline__ void ldsm4(uint32_t addr, uint32_t r[4]) {
    asm volatile("ldmatrix.sync.aligned.m8n8.x4.shared.b16 {%0,%1,%2,%3}, [%4];"
                 : "=r"(r[0]), "=r"(r[1]), "=r"(r[2]), "=r"(r[3]) : "r"(addr));
}
__device__ __forceinline__ void mma16816(float c[4], const uint32_t a[4],
                                         uint32_t b0, uint32_t b1) {
    asm volatile("mma.sync.aligned.m16n8k16.row.col.f32.bf16.bf16.f32 "
                 "{%0,%1,%2,%3}, {%4,%5,%6,%7}, {%8,%9}, {%0,%1,%2,%3};"
                 : "+f"(c[0]), "+f"(c[1]), "+f"(c[2]), "+f"(c[3])
                 : "r"(a[0]), "r"(a[1]), "r"(a[2]), "r"(a[3]), "r"(b0), "r"(b1));
}

// Warp GEMM: D(M32xN32) = A(M32xK128) * W^T(K128xN32), 3-term bf16 split.
// Per k-step: load ALL fragments, then issue MMAs grouped by term so each
// accumulator's reuse distance is 8 (latency hiding).
__device__ __forceinline__ void warp_gemm_split(
    uint32_t aHi, uint32_t aLo, uint32_t wHi, uint32_t wLo,
    int wm, int wn, int lane, float acc[2][4][4])
{
    #pragma unroll
    for (int mt = 0; mt < 2; mt++)
        #pragma unroll
        for (int n8 = 0; n8 < 4; n8++)
            #pragma unroll
            for (int c = 0; c < 4; c++) acc[mt][n8][c] = 0.f;

    int arow[2];
    #pragma unroll
    for (int mt = 0; mt < 2; mt++)
        arow[mt] = wm * 32 + mt * 16 + ((lane >> 3) & 1) * 8 + (lane & 7);
    const int akhi = (lane >> 4) * 8;
    int brow[2];
    #pragma unroll
    for (int np = 0; np < 2; np++)
        brow[np] = wn * 32 + np * 16 + (lane >> 4) * 8 + (lane & 7);
    const int bkhi = ((lane >> 3) & 1) * 8;

    #pragma unroll
    for (int ks = 0; ks < 8; ks++) {
        const int k0 = ks * 16;
        uint32_t ah[2][4], al[2][4], bh[2][4], bl[2][4];
        #pragma unroll
        for (int mt = 0; mt < 2; mt++) {
            uint32_t o = swz(arow[mt], (k0 + akhi) * 2);
            ldsm4(aHi + o, ah[mt]);
            ldsm4(aLo + o, al[mt]);
        }
        #pragma unroll
        for (int np = 0; np < 2; np++) {
            uint32_t bo = swz(brow[np], (k0 + bkhi) * 2);
            ldsm4(wHi + bo, bh[np]);
            ldsm4(wLo + bo, bl[np]);
        }
        // term 1: ah*bh -> 8 independent MMAs
        #pragma unroll
        for (int np = 0; np < 2; np++)
            #pragma unroll
            for (int mt = 0; mt < 2; mt++) {
                mma16816(acc[mt][2 * np],     ah[mt], bh[np][0], bh[np][1]);
                mma16816(acc[mt][2 * np + 1], ah[mt], bh[np][2], bh[np][3]);
            }
        // term 2: al*bh (reuse distance 8)
        #pragma unroll
        for (int np = 0; np < 2; np++)
            #pragma unroll
            for (int mt = 0; mt < 2; mt++) {
                mma16816(acc[mt][2 * np],     al[mt], bh[np][0], bh[np][1]);
                mma16816(acc[mt][2 * np + 1], al[mt], bh[np][2], bh[np][3]);
            }
        // term 3: ah*bl
        #pragma unroll
        for (int np = 0; np < 2; np++)
            #pragma unroll
            for (int mt = 0; mt < 2; mt++) {
                mma16816(acc[mt][2 * np],     ah[mt], bl[np][0], bl[np][1]);
                mma16816(acc[mt][2 * np + 1], ah[mt], bl[np][2], bl[np][3]);
            }
    }
}

// ================= SIMT node kernel (unchanged, proven) =================
#define TMN 64
#define LDA 132
#define LDW 130
struct SmemT {
    float W1T[DIM * LDW];
    float W2T[DIM * LDW];
    float A[TMN * LDA];
    float H[TMN * LDA];
};
__device__ __forceinline__ void pack_dup(unsigned long long& d, float a) {
    unsigned u = __float_as_uint(a);
    asm("mov.b64 %0, {%1, %1};" : "=l"(d) : "r"(u));
}
__device__ __forceinline__ float2 unpack2(unsigned long long v) {
    unsigned lo, hi;
    asm("mov.b64 {%0, %1}, %2;" : "=r"(lo), "=r"(hi) : "l"(v));
    return make_float2(__uint_as_float(lo), __uint_as_float(hi));
}
__device__ __forceinline__ void ffma2(unsigned long long& acc,
                                      unsigned long long a, unsigned long long b) {
    asm("fma.rn.f32x2 %0, %1, %2, %0;" : "+l"(acc) : "l"(a), "l"(b));
}
__device__ __forceinline__ void load_weight_T(float* WT, const float* __restrict__ W, int t) {
    for (int p = t; p < DIM * (DIM / 4); p += NTHREADS) {
        int j = p >> 5, c4 = p & 31;
        float4 v = reinterpret_cast<const float4*>(W)[p];
        int k = c4 * 4;
        WT[(k + 0) * LDW + j] = v.x; WT[(k + 1) * LDW + j] = v.y;
        WT[(k + 2) * LDW + j] = v.z; WT[(k + 3) * LDW + j] = v.w;
    }
}
__device__ __forceinline__ void gemm_tile_x2(const float* __restrict__ A,
                                             const float* __restrict__ WT,
                                             int tx, int ty, unsigned long long acc[4][4]) {
    #pragma unroll 4
    for (int k = 0; k < DIM; k += 2) {
        float2 av[4];
        #pragma unroll
        for (int i = 0; i < 4; i++)
            av[i] = *reinterpret_cast<const float2*>(&A[(ty * 4 + i) * LDA + k]);
        unsigned long long pa0[4], pa1[4];
        #pragma unroll
        for (int i = 0; i < 4; i++) { pack_dup(pa0[i], av[i].x); pack_dup(pa1[i], av[i].y); }
        unsigned long long pb0[4], pb1[4];
        #pragma unroll
        for (int j = 0; j < 4; j++) {
            pb0[j] = *reinterpret_cast<const unsigned long long*>(&WT[(k + 0) * LDW + 2 * tx + 32 * j]);
            pb1[j] = *reinterpret_cast<const unsigned long long*>(&WT[(k + 1) * LDW + 2 * tx + 32 * j]);
        }
        #pragma unroll
        for (int i = 0; i < 4; i++)
            #pragma unroll
            for (int j = 0; j < 4; j++) { ffma2(acc[i][j], pa0[i], pb0[j]); ffma2(acc[i][j], pa1[i], pb1[j]); }
    }
}
__global__ void __launch_bounds__(NTHREADS, 1)
node_kernel(const float* __restrict__ nfeat,
            const float* __restrict__ W_s, const float* __restrict__ W_d)
{
    extern __shared__ char smem_raw[];
    SmemT& sm = *reinterpret_cast<SmemT*>(smem_raw);
    const int t = threadIdx.x;
    const int tx = t & 15, ty = t >> 4;
    load_weight_T(sm.W1T, W_s, t);
    load_weight_T(sm.W2T, W_d, t);
    const int ntiles = (NN + TMN - 1) / TMN;
    for (int tile = blockIdx.x; tile < ntiles; tile += gridDim.x) {
        const int n0 = tile * TMN;
        __syncthreads();
        for (int p = t; p < TMN * (DIM / 4); p += NTHREADS) {
            int r = p >> 5, c4 = p & 31;
            float4 v = make_float4(0.f, 0.f, 0.f, 0.f);
            if (n0 + r < NN)
                v = reinterpret_cast<const float4*>(nfeat)[(size_t)(n0 + r) * 32 + c4];
            *reinterpret_cast<float4*>(&sm.A[r * LDA + c4 * 4]) = v;
        }
        __syncthreads();
        unsigned long long acc[4][4];
        #pragma unroll
        for (int i = 0; i < 4; i++)
            #pragma unroll
            for (int j = 0; j < 4; j++) acc[i][j] = 0ull;
        gemm_tile_x2(sm.A, sm.W1T, tx, ty, acc);
        #pragma unroll
        for (int i = 0; i < 4; i++) {
            int n = n0 + ty * 4 + i;
            if (n < NN)
                #pragma unroll
                for (int j = 0; j < 4; j++) {
                    float2 p = unpack2(acc[i][j]);
                    *reinterpret_cast<float2*>(&g_sproj[(size_t)n * DIM + 2 * tx + 32 * j]) = p;
                }
        }
        #pragma unroll
        for (int i = 0; i < 4; i++)
            #pragma unroll
            for (int j = 0; j < 4; j++) acc[i][j] = 0ull;
        gemm_tile_x2(sm.A, sm.W2T, tx, ty, acc);
        #pragma unroll
        for (int i = 0; i < 4; i++) {
            int n = n0 + ty * 4 + i;
            if (n < NN)
                #pragma unroll
                for (int j = 0; j < 4; j++) {
                    float2 p = unpack2(acc[i][j]);
                    *reinterpret_cast<float2*>(&g_dproj[(size_t)n * DIM + 2 * tx + 32 * j]) = p;
                }
        }
    }
}

// ================= mma.sync edge kernel (512 threads) =================
#define OFF_W1HI 0
#define OFF_W1LO 32768
#define OFF_W2HI 65536
#define OFF_W2LO 98304
#define OFF_AHI  131072
#define OFF_ALO  163840
#define OFF_B1   196608
#define OFF_BO   197120
#define OFF_GM   197632
#define OFF_BT   198144
#define OFF_RSUM 198656   // float[4][128] = 2KB
#define OFF_RSQ  200704   // float[4][128] = 2KB
#define OFF_SRC  202752   // int[128]
#define OFF_DST  203264
#define EDGE_SMEM_BYTES (203776 + 1024)

#define NTILES_E ((NE + 127) / 128)

__global__ void __launch_bounds__(ETHREADS, 1)
edge_mma_kernel(const float* __restrict__ efeat,
                const int* __restrict__ src, const int* __restrict__ dst,
                const float* __restrict__ W_e, const float* __restrict__ b1,
                const float* __restrict__ W_o, const float* __restrict__ b_o,
                const float* __restrict__ gamma, const float* __restrict__ beta,
                float* __restrict__ out)
{
    extern __shared__ char smem_raw[];
    char* ab = (char*)(((uintptr_t)smem_raw + 1023) & ~(uintptr_t)1023);
    const int t = threadIdx.x;
    const int wid = t >> 5, lane = t & 31;
    const int wm = wid & 3, wn = wid >> 2;   // 4x4 warp grid

    const uint32_t u_ahi = smem_u32(ab + OFF_AHI);
    const uint32_t u_alo = smem_u32(ab + OFF_ALO);
    const uint32_t u_w1h = smem_u32(ab + OFF_W1HI);
    const uint32_t u_w1l = smem_u32(ab + OFF_W1LO);
    const uint32_t u_w2h = smem_u32(ab + OFF_W2HI);
    const uint32_t u_w2l = smem_u32(ab + OFF_W2LO);

    float* b1s = (float*)(ab + OFF_B1);
    float* bos = (float*)(ab + OFF_BO);
    float* gms = (float*)(ab + OFF_GM);
    float* bts = (float*)(ab + OFF_BT);
    float* rsum = (float*)(ab + OFF_RSUM);
    float* rsq  = (float*)(ab + OFF_RSQ);
    int* srcS = (int*)(ab + OFF_SRC);
    int* dstS = (int*)(ab + OFF_DST);

    load_split_matrix(ab + OFF_W1HI, ab + OFF_W1LO, W_e, t, ETHREADS);
    load_split_matrix(ab + OFF_W2HI, ab + OFF_W2LO, W_o, t, ETHREADS);
    if (t < 128) { b1s[t] = b1[t]; bos[t] = b_o[t]; gms[t] = gamma[t]; bts[t] = beta[t]; }

    const int quad = lane >> 2, qt = lane & 3;

    for (int tile = blockIdx.x; tile < NTILES_E; tile += gridDim.x) {
        const int e0 = tile * 128;
        __syncthreads();  // previous tile fully consumed

        // ---- load + split efeat tile; load indices
        for (int p = t; p < DIM * 32; p += ETHREADS) {
            int r = p >> 5, c4 = p & 31;
            int e = e0 + r;
            float4 v = make_float4(0.f, 0.f, 0.f, 0.f);
            if (e < NE) v = reinterpret_cast<const float4*>(efeat)[(size_t)e * 32 + c4];
            __nv_bfloat16 h0, l0, h1, l1, h2, l2, h3, l3;
            split_bf16(v.x, h0, l0); split_bf16(v.y, h1, l1);
            split_bf16(v.z, h2, l2); split_bf16(v.w, h3, l3);
            uint32_t o = swz(r, c4 * 8);
            *reinterpret_cast<__nv_bfloat162*>(ab + OFF_AHI + o)     = __nv_bfloat162(h0, h1);
            *reinterpret_cast<__nv_bfloat162*>(ab + OFF_AHI + o + 4) = __nv_bfloat162(h2, h3);
            *reinterpret_cast<__nv_bfloat162*>(ab + OFF_ALO + o)     = __nv_bfloat162(l0, l1);
            *reinterpret_cast<__nv_bfloat162*>(ab + OFF_ALO + o + 4) = __nv_bfloat162(l2, l3);
        }
        if (t < 128) {
            int e = e0 + t;
            srcS[t] = (e < NE) ? src[e] : 0;
            dstS[t] = (e < NE) ? dst[e] : 0;
        }
        __syncthreads();

        // ---- GEMM1
        float acc[2][4][4];
        warp_gemm_split(u_ahi, u_alo, u_w1h, u_w1l, wm, wn, lane, acc);
        __syncthreads();  // all warps done reading A before H overwrite

        // ---- epilogue 1: + b1 + gathers, SiLU, split -> H into A buffers
        #pragma unroll
        for (int mt = 0; mt < 2; mt++) {
            #pragma unroll
            for (int rh = 0; rh < 2; rh++) {
                int row = wm * 32 + mt * 16 + quad + rh * 8;
                const float* sp = g_sproj + (size_t)srcS[row] * DIM;
                const float* dp = g_dproj + (size_t)dstS[row] * DIM;
                #pragma unroll
                for (int n8 = 0; n8 < 4; n8++) {
                    int col = wn * 32 + n8 * 8 + 2 * qt;
                    float2 s2 = *reinterpret_cast<const float2*>(&sp[col]);
                    float2 d2 = *reinterpret_cast<const float2*>(&dp[col]);
                    float2 b2 = *reinterpret_cast<const float2*>(&b1s[col]);
                    float x0 = acc[mt][n8][rh * 2 + 0] + b2.x + s2.x + d2.x;
                    float x1 = acc[mt][n8][rh * 2 + 1] + b2.y + s2.y + d2.y;
                    float v0 = x0 / (1.0f + __expf(-x0));
                    float v1 = x1 / (1.0f + __expf(-x1));
                    __nv_bfloat16 h0, l0, h1, l1;
                    split_bf16(v0, h0, l0); split_bf16(v1, h1, l1);
                    uint32_t o = swz(row, col * 2);
                    *reinterpret_cast<__nv_bfloat162*>(ab + OFF_AHI + o) = __nv_bfloat162(h0, h1);
                    *reinterpret_cast<__nv_bfloat162*>(ab + OFF_ALO + o) = __nv_bfloat162(l0, l1);
                }
            }
        }
        __syncthreads();

        // ---- GEMM2
        warp_gemm_split(u_ahi, u_alo, u_w2h, u_w2l, wm, wn, lane, acc);

        // ---- epilogue 2: + b_o, LayerNorm partials (32-col group per warp)
        #pragma unroll
        for (int mt = 0; mt < 2; mt++) {
            #pragma unroll
            for (int rh = 0; rh < 2; rh++) {
                int row = wm * 32 + mt * 16 + quad + rh * 8;
                float s = 0.f, q = 0.f;
                #pragma unroll
                for (int n8 = 0; n8 < 4; n8++) {
                    int col = wn * 32 + n8 * 8 + 2 * qt;
                    float2 b2 = *reinterpret_cast<const float2*>(&bos[col]);
                    float v0 = acc[mt][n8][rh * 2 + 0] + b2.x;
                    float v1 = acc[mt][n8][rh * 2 + 1] + b2.y;
                    acc[mt][n8][rh * 2 + 0] = v0;
                    acc[mt][n8][rh * 2 + 1] = v1;
                    s += v0 + v1;
                    q += v0 * v0 + v1 * v1;
                }
                s += __shfl_xor_sync(0xffffffffu, s, 1);
                s += __shfl_xor_sync(0xffffffffu, s, 2);
                q += __shfl_xor_sync(0xffffffffu, q, 1);
                q += __shfl_xor_sync(0xffffffffu, q, 2);
                if (qt == 0) {
                    rsum[wn * 128 + row] = s;
                    rsq[wn * 128 + row] = q;
                }
            }
        }
        __syncthreads();

        // ---- normalize + affine + residual + store
        #pragma unroll
        for (int mt = 0; mt < 2; mt++) {
            #pragma unroll
            for (int rh = 0; rh < 2; rh++) {
                int row = wm * 32 + mt * 16 + quad + rh * 8;
                int e = e0 + row;
                if (e >= NE) continue;
                float ts = rsum[row] + rsum[128 + row] + rsum[256 + row] + rsum[384 + row];
                float tq = rsq[row] + rsq[128 + row] + rsq[256 + row] + rsq[384 + row];
                float mean = ts * (1.0f / 128.0f);
                float var = tq * (1.0f / 128.0f) - mean * mean;
                float rstd = rsqrtf(var + 1e-5f);
                #pragma unroll
                for (int n8 = 0; n8 < 4; n8++) {
                    int col = wn * 32 + n8 * 8 + 2 * qt;
                    float2 g2 = *reinterpret_cast<const float2*>(&gms[col]);
                    float2 t2 = *reinterpret_cast<const float2*>(&bts[col]);
                    float2 r2 = *reinterpret_cast<const float2*>(&efeat[(size_t)e * DIM + col]);
                    float o0 = (acc[mt][n8][rh * 2 + 0] - mean) * rstd * g2.x + t2.x + r2.x;
                    float o1 = (acc[mt][n8][rh * 2 + 1] - mean) * rstd * g2.y + t2.y + r2.y;
                    *reinterpret_cast<float2*>(&out[(size_t)e * DIM + col]) = make_float2(o0, o1);
                }
            }
        }
    }
}

extern "C" void kernel_launch(void* const* d_in, const int* in_sizes, int n_in,
                              void* d_out, int out_size) {
    const float* efeat = (const float*)d_in[0];
    const float* nfeat = (const float*)d_in[1];
    const int*   src   = (const int*)d_in[2];
    const int*   dst   = (const int*)d_in[3];
    const float* W_e   = (const float*)d_in[4];
    const float* W_s   = (const float*)d_in[5];
    const float* W_d   = (const float*)d_in[6];
    const float* b1    = (const float*)d_in[7];
    const float* W_o   = (const float*)d_in[8];
    const float* b_o   = (const float*)d_in[9];
    const float* gamma = (const float*)d_in[10];
    const float* beta  = (const float*)d_in[11];
    float* out = (float*)d_out;

    int smemN = (int)sizeof(SmemT);
    cudaFuncSetAttribute(node_kernel, cudaFuncAttributeMaxDynamicSharedMemorySize, smemN);
    cudaFuncSetAttribute(edge_mma_kernel, cudaFuncAttributeMaxDynamicSharedMemorySize,
                         EDGE_SMEM_BYTES);

    node_kernel<<<NSM, NTHREADS, smemN>>>(nfeat, W_s, W_d);
    edge_mma_kernel<<<NSM, ETHREADS, EDGE_SMEM_BYTES>>>(efeat, src, dst, W_e, b1, W_o, b_o,
                                                        gamma, beta, out);
    cudaMemcpyAsync(out + (size_t)NE * DIM, nfeat,
                    (size_t)NN * DIM * sizeof(float), cudaMemcpyDeviceToDevice);
}

// round 10
// speedup vs baseline: 1.7528x; 1.1266x over previous
#include <cuda_runtime.h>
#include <cuda_bf16.h>
#include <cstdint>

#define NE 600000
#define NN 50000
#define DIM 128
#define ETHREADS 1024
#define NSM 152

// Scratch for node projections
__device__ float g_sproj[(size_t)NN * DIM];
__device__ float g_dproj[(size_t)NN * DIM];

// ---------------- common helpers ----------------
__device__ __forceinline__ uint32_t smem_u32(const void* p) {
    uint32_t a;
    asm("{ .reg .u64 t; cvta.to.shared.u64 t, %1; cvt.u32.u64 %0, t; }" : "=r"(a) : "l"(p));
    return a;
}

// Swizzled tile layout: 128 rows x 128 bf16, row stride 256B.
// 16B chunk index c (0..15) -> (c&8) | ((c ^ r) & 7): ldmatrix conflict-free.
__device__ __forceinline__ uint32_t swz(int r, int kb) {
    int chunk = kb >> 4;
    int c2 = (chunk & 8) | ((chunk ^ r) & 7);
    return (uint32_t)(r * 256 + c2 * 16 + (kb & 15));
}

__device__ __forceinline__ void split_bf16(float x, __nv_bfloat16& h, __nv_bfloat16& l) {
    h = __float2bfloat16_rn(x);
    l = __float2bfloat16_rn(x - __bfloat162float(h));
}

// load 128x128 fp32 row-major matrix, split into hi/lo bf16 swizzled tiles
__device__ __forceinline__ void load_split_matrix(char* hiB, char* loB,
                                                  const float* __restrict__ W,
                                                  int t, int nthr) {
    for (int p = t; p < DIM * (DIM / 4); p += nthr) {
        int r = p >> 5, c4 = p & 31;
        float4 v = reinterpret_cast<const float4*>(W)[p];
        __nv_bfloat16 h0, l0, h1, l1, h2, l2, h3, l3;
        split_bf16(v.x, h0, l0); split_bf16(v.y, h1, l1);
        split_bf16(v.z, h2, l2); split_bf16(v.w, h3, l3);
        uint32_t o = swz(r, c4 * 8);
        *reinterpret_cast<__nv_bfloat162*>(hiB + o)     = __nv_bfloat162(h0, h1);
        *reinterpret_cast<__nv_bfloat162*>(hiB + o + 4) = __nv_bfloat162(h2, h3);
        *reinterpret_cast<__nv_bfloat162*>(loB + o)     = __nv_bfloat162(l0, l1);
        *reinterpret_cast<__nv_bfloat162*>(loB + o + 4) = __nv_bfloat162(l2, l3);
    }
}

__device__ __forceinline__ void ldsm4(uint32_t addr, uint32_t r[4]) {
    asm volatile("ldmatrix.sync.aligned.m8n8.x4.shared.b16 {%0,%1,%2,%3}, [%4];"
                 : "=r"(r[0]), "=r"(r[1]), "=r"(r[2]), "=r"(r[3]) : "r"(addr));
}
__device__ __forceinline__ void mma16816(float c[4], const uint32_t a[4],
                                         uint32_t b0, uint32_t b1) {
    asm volatile("mma.sync.aligned.m16n8k16.row.col.f32.bf16.bf16.f32 "
                 "{%0,%1,%2,%3}, {%4,%5,%6,%7}, {%8,%9}, {%0,%1,%2,%3};"
                 : "+f"(c[0]), "+f"(c[1]), "+f"(c[2]), "+f"(c[3])
                 : "r"(a[0]), "r"(a[1]), "r"(a[2]), "r"(a[3]), "r"(b0), "r"(b1));
}

// Warp GEMM: D(M32xN16) = A(M32xK128) * W^T(K128xN16), 3-term bf16 split.
// 4x8 warp grid over the 128x128 tile. MMAs grouped by term for ILP.
__device__ __forceinline__ void warp_gemm_split(
    uint32_t aHi, uint32_t aLo, uint32_t wHi, uint32_t wLo,
    int wm, int wn, int lane, float acc[2][2][4])
{
    #pragma unroll
    for (int mt = 0; mt < 2; mt++)
        #pragma unroll
        for (int n8 = 0; n8 < 2; n8++)
            #pragma unroll
            for (int c = 0; c < 4; c++) acc[mt][n8][c] = 0.f;

    int arow[2];
    #pragma unroll
    for (int mt = 0; mt < 2; mt++)
        arow[mt] = wm * 32 + mt * 16 + ((lane >> 3) & 1) * 8 + (lane & 7);
    const int akhi = (lane >> 4) * 8;
    const int brow = wn * 16 + (lane >> 4) * 8 + (lane & 7);
    const int bkhi = ((lane >> 3) & 1) * 8;

    #pragma unroll
    for (int ks = 0; ks < 8; ks++) {
        const int k0 = ks * 16;
        uint32_t ah[2][4], al[2][4], bh[4], bl[4];
        #pragma unroll
        for (int mt = 0; mt < 2; mt++) {
            uint32_t o = swz(arow[mt], (k0 + akhi) * 2);
            ldsm4(aHi + o, ah[mt]);
            ldsm4(aLo + o, al[mt]);
        }
        {
            uint32_t bo = swz(brow, (k0 + bkhi) * 2);
            ldsm4(wHi + bo, bh);
            ldsm4(wLo + bo, bl);
        }
        // term 1: ah*bh (4 independent)
        #pragma unroll
        for (int mt = 0; mt < 2; mt++) {
            mma16816(acc[mt][0], ah[mt], bh[0], bh[1]);
            mma16816(acc[mt][1], ah[mt], bh[2], bh[3]);
        }
        // term 2: al*bh
        #pragma unroll
        for (int mt = 0; mt < 2; mt++) {
            mma16816(acc[mt][0], al[mt], bh[0], bh[1]);
            mma16816(acc[mt][1], al[mt], bh[2], bh[3]);
        }
        // term 3: ah*bl
        #pragma unroll
        for (int mt = 0; mt < 2; mt++) {
            mma16816(acc[mt][0], ah[mt], bl[0], bl[1]);
            mma16816(acc[mt][1], ah[mt], bl[2], bl[3]);
        }
    }
}

// ================= tensor node kernel =================
// SMEM: WS hi/lo, WD hi/lo (4 x 32KB), A hi/lo (2 x 32KB)
#define NOFF_WSH 0
#define NOFF_WSL 32768
#define NOFF_WDH 65536
#define NOFF_WDL 98304
#define NOFF_AHI 131072
#define NOFF_ALO 163840
#define NODE_SMEM_BYTES (196608 + 1024)
#define NTILES_N ((NN + 127) / 128)

__global__ void __launch_bounds__(ETHREADS, 1)
node_mma_kernel(const float* __restrict__ nfeat,
                const float* __restrict__ W_s, const float* __restrict__ W_d)
{
    extern __shared__ char smem_raw[];
    char* ab = (char*)(((uintptr_t)smem_raw + 1023) & ~(uintptr_t)1023);
    const int t = threadIdx.x;
    const int wid = t >> 5, lane = t & 31;
    const int wm = wid & 3, wn = wid >> 2;
    const int quad = lane >> 2, qt = lane & 3;

    const uint32_t u_ahi = smem_u32(ab + NOFF_AHI);
    const uint32_t u_alo = smem_u32(ab + NOFF_ALO);
    const uint32_t u_wsh = smem_u32(ab + NOFF_WSH);
    const uint32_t u_wsl = smem_u32(ab + NOFF_WSL);
    const uint32_t u_wdh = smem_u32(ab + NOFF_WDH);
    const uint32_t u_wdl = smem_u32(ab + NOFF_WDL);

    load_split_matrix(ab + NOFF_WSH, ab + NOFF_WSL, W_s, t, ETHREADS);
    load_split_matrix(ab + NOFF_WDH, ab + NOFF_WDL, W_d, t, ETHREADS);

    for (int tile = blockIdx.x; tile < NTILES_N; tile += gridDim.x) {
        const int n0 = tile * 128;
        __syncthreads();
        for (int p = t; p < DIM * 32; p += ETHREADS) {
            int r = p >> 5, c4 = p & 31;
            int n = n0 + r;
            float4 v = make_float4(0.f, 0.f, 0.f, 0.f);
            if (n < NN) v = reinterpret_cast<const float4*>(nfeat)[(size_t)n * 32 + c4];
            __nv_bfloat16 h0, l0, h1, l1, h2, l2, h3, l3;
            split_bf16(v.x, h0, l0); split_bf16(v.y, h1, l1);
            split_bf16(v.z, h2, l2); split_bf16(v.w, h3, l3);
            uint32_t o = swz(r, c4 * 8);
            *reinterpret_cast<__nv_bfloat162*>(ab + NOFF_AHI + o)     = __nv_bfloat162(h0, h1);
            *reinterpret_cast<__nv_bfloat162*>(ab + NOFF_AHI + o + 4) = __nv_bfloat162(h2, h3);
            *reinterpret_cast<__nv_bfloat162*>(ab + NOFF_ALO + o)     = __nv_bfloat162(l0, l1);
            *reinterpret_cast<__nv_bfloat162*>(ab + NOFF_ALO + o + 4) = __nv_bfloat162(l2, l3);
        }
        __syncthreads();

        float acc[2][2][4];
        warp_gemm_split(u_ahi, u_alo, u_wsh, u_wsl, wm, wn, lane, acc);
        #pragma unroll
        for (int mt = 0; mt < 2; mt++)
            #pragma unroll
            for (int rh = 0; rh < 2; rh++) {
                int n = n0 + wm * 32 + mt * 16 + quad + rh * 8;
                if (n < NN)
                    #pragma unroll
                    for (int n8 = 0; n8 < 2; n8++) {
                        int col = wn * 16 + n8 * 8 + 2 * qt;
                        *reinterpret_cast<float2*>(&g_sproj[(size_t)n * DIM + col]) =
                            make_float2(acc[mt][n8][rh * 2], acc[mt][n8][rh * 2 + 1]);
                    }
            }

        warp_gemm_split(u_ahi, u_alo, u_wdh, u_wdl, wm, wn, lane, acc);
        #pragma unroll
        for (int mt = 0; mt < 2; mt++)
            #pragma unroll
            for (int rh = 0; rh < 2; rh++) {
                int n = n0 + wm * 32 + mt * 16 + quad + rh * 8;
                if (n < NN)
                    #pragma unroll
                    for (int n8 = 0; n8 < 2; n8++) {
                        int col = wn * 16 + n8 * 8 + 2 * qt;
                        *reinterpret_cast<float2*>(&g_dproj[(size_t)n * DIM + col]) =
                            make_float2(acc[mt][n8][rh * 2], acc[mt][n8][rh * 2 + 1]);
                    }
            }
    }
}

// ================= mma.sync edge kernel (1024 threads) =================
#define OFF_W1HI 0
#define OFF_W1LO 32768
#define OFF_W2HI 65536
#define OFF_W2LO 98304
#define OFF_AHI  131072
#define OFF_ALO  163840
#define OFF_B1   196608
#define OFF_BO   197120
#define OFF_GM   197632
#define OFF_BT   198144
#define OFF_RSUM 198656   // float[8][128] = 4KB
#define OFF_RSQ  202752   // float[8][128] = 4KB
#define OFF_SRC  206848   // int[128]
#define OFF_DST  207360
#define EDGE_SMEM_BYTES (207872 + 1024)

#define NTILES_E ((NE + 127) / 128)

__global__ void __launch_bounds__(ETHREADS, 1)
edge_mma_kernel(const float* __restrict__ efeat,
                const int* __restrict__ src, const int* __restrict__ dst,
                const float* __restrict__ W_e, const float* __restrict__ b1,
                const float* __restrict__ W_o, const float* __restrict__ b_o,
                const float* __restrict__ gamma, const float* __restrict__ beta,
                float* __restrict__ out)
{
    extern __shared__ char smem_raw[];
    char* ab = (char*)(((uintptr_t)smem_raw + 1023) & ~(uintptr_t)1023);
    const int t = threadIdx.x;
    const int wid = t >> 5, lane = t & 31;
    const int wm = wid & 3, wn = wid >> 2;   // 4(M) x 8(N) warp grid

    const uint32_t u_ahi = smem_u32(ab + OFF_AHI);
    const uint32_t u_alo = smem_u32(ab + OFF_ALO);
    const uint32_t u_w1h = smem_u32(ab + OFF_W1HI);
    const uint32_t u_w1l = smem_u32(ab + OFF_W1LO);
    const uint32_t u_w2h = smem_u32(ab + OFF_W2HI);
    const uint32_t u_w2l = smem_u32(ab + OFF_W2LO);

    float* b1s = (float*)(ab + OFF_B1);
    float* bos = (float*)(ab + OFF_BO);
    float* gms = (float*)(ab + OFF_GM);
    float* bts = (float*)(ab + OFF_BT);
    float* rsum = (float*)(ab + OFF_RSUM);
    float* rsq  = (float*)(ab + OFF_RSQ);
    int* srcS = (int*)(ab + OFF_SRC);
    int* dstS = (int*)(ab + OFF_DST);

    load_split_matrix(ab + OFF_W1HI, ab + OFF_W1LO, W_e, t, ETHREADS);
    load_split_matrix(ab + OFF_W2HI, ab + OFF_W2LO, W_o, t, ETHREADS);
    if (t < 128) { b1s[t] = b1[t]; bos[t] = b_o[t]; gms[t] = gamma[t]; bts[t] = beta[t]; }

    const int quad = lane >> 2, qt = lane & 3;

    for (int tile = blockIdx.x; tile < NTILES_E; tile += gridDim.x) {
        const int e0 = tile * 128;
        __syncthreads();  // previous tile fully consumed

        // ---- load + split efeat tile; load indices
        for (int p = t; p < DIM * 32; p += ETHREADS) {
            int r = p >> 5, c4 = p & 31;
            int e = e0 + r;
            float4 v = make_float4(0.f, 0.f, 0.f, 0.f);
            if (e < NE) v = reinterpret_cast<const float4*>(efeat)[(size_t)e * 32 + c4];
            __nv_bfloat16 h0, l0, h1, l1, h2, l2, h3, l3;
            split_bf16(v.x, h0, l0); split_bf16(v.y, h1, l1);
            split_bf16(v.z, h2, l2); split_bf16(v.w, h3, l3);
            uint32_t o = swz(r, c4 * 8);
            *reinterpret_cast<__nv_bfloat162*>(ab + OFF_AHI + o)     = __nv_bfloat162(h0, h1);
            *reinterpret_cast<__nv_bfloat162*>(ab + OFF_AHI + o + 4) = __nv_bfloat162(h2, h3);
            *reinterpret_cast<__nv_bfloat162*>(ab + OFF_ALO + o)     = __nv_bfloat162(l0, l1);
            *reinterpret_cast<__nv_bfloat162*>(ab + OFF_ALO + o + 4) = __nv_bfloat162(l2, l3);
        }
        if (t < 128) {
            int e = e0 + t;
            srcS[t] = (e < NE) ? src[e] : 0;
            dstS[t] = (e < NE) ? dst[e] : 0;
        }
        __syncthreads();

        // ---- GEMM1
        float acc[2][2][4];
        warp_gemm_split(u_ahi, u_alo, u_w1h, u_w1l, wm, wn, lane, acc);
        __syncthreads();  // all warps done reading A before H overwrite

        // ---- epilogue 1: + b1 + gathers, SiLU, split -> H into A buffers
        #pragma unroll
        for (int mt = 0; mt < 2; mt++) {
            #pragma unroll
            for (int rh = 0; rh < 2; rh++) {
                int row = wm * 32 + mt * 16 + quad + rh * 8;
                const float* sp = g_sproj + (size_t)srcS[row] * DIM;
                const float* dp = g_dproj + (size_t)dstS[row] * DIM;
                #pragma unroll
                for (int n8 = 0; n8 < 2; n8++) {
                    int col = wn * 16 + n8 * 8 + 2 * qt;
                    float2 s2 = *reinterpret_cast<const float2*>(&sp[col]);
                    float2 d2 = *reinterpret_cast<const float2*>(&dp[col]);
                    float2 b2 = *reinterpret_cast<const float2*>(&b1s[col]);
                    float x0 = acc[mt][n8][rh * 2 + 0] + b2.x + s2.x + d2.x;
                    float x1 = acc[mt][n8][rh * 2 + 1] + b2.y + s2.y + d2.y;
                    float v0 = x0 / (1.0f + __expf(-x0));
                    float v1 = x1 / (1.0f + __expf(-x1));
                    __nv_bfloat16 h0, l0, h1, l1;
                    split_bf16(v0, h0, l0); split_bf16(v1, h1, l1);
                    uint32_t o = swz(row, col * 2);
                    *reinterpret_cast<__nv_bfloat162*>(ab + OFF_AHI + o) = __nv_bfloat162(h0, h1);
                    *reinterpret_cast<__nv_bfloat162*>(ab + OFF_ALO + o) = __nv_bfloat162(l0, l1);
                }
            }
        }
        __syncthreads();

        // ---- GEMM2
        warp_gemm_split(u_ahi, u_alo, u_w2h, u_w2l, wm, wn, lane, acc);

        // ---- epilogue 2: + b_o, LayerNorm partials (16-col group per warp)
        #pragma unroll
        for (int mt = 0; mt < 2; mt++) {
            #pragma unroll
            for (int rh = 0; rh < 2; rh++) {
                int row = wm * 32 + mt * 16 + quad + rh * 8;
                float s = 0.f, q = 0.f;
                #pragma unroll
                for (int n8 = 0; n8 < 2; n8++) {
                    int col = wn * 16 + n8 * 8 + 2 * qt;
                    float2 b2 = *reinterpret_cast<const float2*>(&bos[col]);
                    float v0 = acc[mt][n8][rh * 2 + 0] + b2.x;
                    float v1 = acc[mt][n8][rh * 2 + 1] + b2.y;
                    acc[mt][n8][rh * 2 + 0] = v0;
                    acc[mt][n8][rh * 2 + 1] = v1;
                    s += v0 + v1;
                    q += v0 * v0 + v1 * v1;
                }
                s += __shfl_xor_sync(0xffffffffu, s, 1);
                s += __shfl_xor_sync(0xffffffffu, s, 2);
                q += __shfl_xor_sync(0xffffffffu, q, 1);
                q += __shfl_xor_sync(0xffffffffu, q, 2);
                if (qt == 0) {
                    rsum[wn * 128 + row] = s;
                    rsq[wn * 128 + row] = q;
                }
            }
        }
        __syncthreads();

        // ---- normalize + affine + residual + store
        #pragma unroll
        for (int mt = 0; mt < 2; mt++) {
            #pragma unroll
            for (int rh = 0; rh < 2; rh++) {
                int row = wm * 32 + mt * 16 + quad + rh * 8;
                int e = e0 + row;
                if (e >= NE) continue;
                float ts = 0.f, tq = 0.f;
                #pragma unroll
                for (int sgm = 0; sgm < 8; sgm++) {
                    ts += rsum[sgm * 128 + row];
                    tq += rsq[sgm * 128 + row];
                }
                float mean = ts * (1.0f / 128.0f);
                float var = tq * (1.0f / 128.0f) - mean * mean;
                float rstd = rsqrtf(var + 1e-5f);
                #pragma unroll
                for (int n8 = 0; n8 < 2; n8++) {
                    int col = wn * 16 + n8 * 8 + 2 * qt;
                    float2 g2 = *reinterpret_cast<const float2*>(&gms[col]);
                    float2 t2 = *reinterpret_cast<const float2*>(&bts[col]);
                    float2 r2 = *reinterpret_cast<const float2*>(&efeat[(size_t)e * DIM + col]);
                    float o0 = (acc[mt][n8][rh * 2 + 0] - mean) * rstd * g2.x + t2.x + r2.x;
                    float o1 = (acc[mt][n8][rh * 2 + 1] - mean) * rstd * g2.y + t2.y + r2.y;
                    *reinterpret_cast<float2*>(&out[(size_t)e * DIM + col]) = make_float2(o0, o1);
                }
            }
        }
    }
}

extern "C" void kernel_launch(void* const* d_in, const int* in_sizes, int n_in,
                              void* d_out, int out_size) {
    const float* efeat = (const float*)d_in[0];
    const float* nfeat = (const float*)d_in[1];
    const int*   src   = (const int*)d_in[2];
    const int*   dst   = (const int*)d_in[3];
    const float* W_e   = (const float*)d_in[4];
    const float* W_s   = (const float*)d_in[5];
    const float* W_d   = (const float*)d_in[6];
    const float* b1    = (const float*)d_in[7];
    const float* W_o   = (const float*)d_in[8];
    const float* b_o   = (const float*)d_in[9];
    const float* gamma = (const float*)d_in[10];
    const float* beta  = (const float*)d_in[11];
    float* out = (float*)d_out;

    cudaFuncSetAttribute(node_mma_kernel, cudaFuncAttributeMaxDynamicSharedMemorySize,
                         NODE_SMEM_BYTES);
    cudaFuncSetAttribute(edge_mma_kernel, cudaFuncAttributeMaxDynamicSharedMemorySize,
                         EDGE_SMEM_BYTES);

    node_mma_kernel<<<NSM, ETHREADS, NODE_SMEM_BYTES>>>(nfeat, W_s, W_d);
    edge_mma_kernel<<<NSM, ETHREADS, EDGE_SMEM_BYTES>>>(efeat, src, dst, W_e, b1, W_o, b_o,
                                                        gamma, beta, out);
    cudaMemcpyAsync(out + (size_t)NE * DIM, nfeat,
                    (size_t)NN * DIM * sizeof(float), cudaMemcpyDeviceToDevice);
}

// round 11
// speedup vs baseline: 1.8022x; 1.0282x over previous
#include <cuda_runtime.h>
#include <cuda_bf16.h>
#include <cstdint>

#define NE 600000
#define NN 50000
#define DIM 128
#define NTHREADS 1024
#define ETHREADS 640
#define ETM 160
#define NSM 152

// Scratch for node projections
__device__ float g_sproj[(size_t)NN * DIM];
__device__ float g_dproj[(size_t)NN * DIM];

// ---------------- common helpers ----------------
__device__ __forceinline__ uint32_t smem_u32(const void* p) {
    uint32_t a;
    asm("{ .reg .u64 t; cvta.to.shared.u64 t, %1; cvt.u32.u64 %0, t; }" : "=r"(a) : "l"(p));
    return a;
}

// Swizzled tile layout: rows x 128 bf16, row stride 256B.
// 16B chunk index c (0..15) -> (c&8) | ((c ^ r) & 7): ldmatrix conflict-free.
__device__ __forceinline__ uint32_t swz(int r, int kb) {
    int chunk = kb >> 4;
    int c2 = (chunk & 8) | ((chunk ^ r) & 7);
    return (uint32_t)(r * 256 + c2 * 16 + (kb & 15));
}

__device__ __forceinline__ void split_bf16(float x, __nv_bfloat16& h, __nv_bfloat16& l) {
    h = __float2bfloat16_rn(x);
    l = __float2bfloat16_rn(x - __bfloat162float(h));
}

// load 128x128 fp32 row-major matrix, split into hi/lo bf16 swizzled tiles
__device__ __forceinline__ void load_split_matrix(char* hiB, char* loB,
                                                  const float* __restrict__ W,
                                                  int t, int nthr) {
    for (int p = t; p < DIM * (DIM / 4); p += nthr) {
        int r = p >> 5, c4 = p & 31;
        float4 v = reinterpret_cast<const float4*>(W)[p];
        __nv_bfloat16 h0, l0, h1, l1, h2, l2, h3, l3;
        split_bf16(v.x, h0, l0); split_bf16(v.y, h1, l1);
        split_bf16(v.z, h2, l2); split_bf16(v.w, h3, l3);
        uint32_t o = swz(r, c4 * 8);
        *reinterpret_cast<__nv_bfloat162*>(hiB + o)     = __nv_bfloat162(h0, h1);
        *reinterpret_cast<__nv_bfloat162*>(hiB + o + 4) = __nv_bfloat162(h2, h3);
        *reinterpret_cast<__nv_bfloat162*>(loB + o)     = __nv_bfloat162(l0, l1);
        *reinterpret_cast<__nv_bfloat162*>(loB + o + 4) = __nv_bfloat162(l2, l3);
    }
}

__device__ __forceinline__ void ldsm4(uint32_t addr, uint32_t r[4]) {
    asm volatile("ldmatrix.sync.aligned.m8n8.x4.shared.b16 {%0,%1,%2,%3}, [%4];"
                 : "=r"(r[0]), "=r"(r[1]), "=r"(r[2]), "=r"(r[3]) : "r"(addr));
}
__device__ __forceinline__ void mma16816(float c[4], const uint32_t a[4],
                                         uint32_t b0, uint32_t b1) {
    asm volatile("mma.sync.aligned.m16n8k16.row.col.f32.bf16.bf16.f32 "
                 "{%0,%1,%2,%3}, {%4,%5,%6,%7}, {%8,%9}, {%0,%1,%2,%3};"
                 : "+f"(c[0]), "+f"(c[1]), "+f"(c[2]), "+f"(c[3])
                 : "r"(a[0]), "r"(a[1]), "r"(a[2]), "r"(a[3]), "r"(b0), "r"(b1));
}

// Warp GEMM: D(M32xN32) = A(M32xK128) * W^T(K128xN32), 3-term bf16 split.
// MMAs grouped by term so each accumulator's reuse distance is 8.
__device__ __forceinline__ void warp_gemm_split32(
    uint32_t aHi, uint32_t aLo, uint32_t wHi, uint32_t wLo,
    int wm, int wn, int lane, float acc[2][4][4])
{
    #pragma unroll
    for (int mt = 0; mt < 2; mt++)
        #pragma unroll
        for (int n8 = 0; n8 < 4; n8++)
            #pragma unroll
            for (int c = 0; c < 4; c++) acc[mt][n8][c] = 0.f;

    int arow[2];
    #pragma unroll
    for (int mt = 0; mt < 2; mt++)
        arow[mt] = wm * 32 + mt * 16 + ((lane >> 3) & 1) * 8 + (lane & 7);
    const int akhi = (lane >> 4) * 8;
    int brow[2];
    #pragma unroll
    for (int np = 0; np < 2; np++)
        brow[np] = wn * 32 + np * 16 + (lane >> 4) * 8 + (lane & 7);
    const int bkhi = ((lane >> 3) & 1) * 8;

    #pragma unroll
    for (int ks = 0; ks < 8; ks++) {
        const int k0 = ks * 16;
        uint32_t ah[2][4], al[2][4], bh[2][4], bl[2][4];
        #pragma unroll
        for (int mt = 0; mt < 2; mt++) {
            uint32_t o = swz(arow[mt], (k0 + akhi) * 2);
            ldsm4(aHi + o, ah[mt]);
            ldsm4(aLo + o, al[mt]);
        }
        #pragma unroll
        for (int np = 0; np < 2; np++) {
            uint32_t bo = swz(brow[np], (k0 + bkhi) * 2);
            ldsm4(wHi + bo, bh[np]);
            ldsm4(wLo + bo, bl[np]);
        }
        // term 1: ah*bh (8 independent)
        #pragma unroll
        for (int np = 0; np < 2; np++)
            #pragma unroll
            for (int mt = 0; mt < 2; mt++) {
                mma16816(acc[mt][2 * np],     ah[mt], bh[np][0], bh[np][1]);
                mma16816(acc[mt][2 * np + 1], ah[mt], bh[np][2], bh[np][3]);
            }
        // term 2: al*bh
        #pragma unroll
        for (int np = 0; np < 2; np++)
            #pragma unroll
            for (int mt = 0; mt < 2; mt++) {
                mma16816(acc[mt][2 * np],     al[mt], bh[np][0], bh[np][1]);
                mma16816(acc[mt][2 * np + 1], al[mt], bh[np][2], bh[np][3]);
            }
        // term 3: ah*bl
        #pragma unroll
        for (int np = 0; np < 2; np++)
            #pragma unroll
            for (int mt = 0; mt < 2; mt++) {
                mma16816(acc[mt][2 * np],     ah[mt], bl[np][0], bl[np][1]);
                mma16816(acc[mt][2 * np + 1], ah[mt], bl[np][2], bl[np][3]);
            }
    }
}

// Warp GEMM: D(M32xN16), used by node kernel (4x8 warp grid, 1024 threads).
__device__ __forceinline__ void warp_gemm_split16(
    uint32_t aHi, uint32_t aLo, uint32_t wHi, uint32_t wLo,
    int wm, int wn, int lane, float acc[2][2][4])
{
    #pragma unroll
    for (int mt = 0; mt < 2; mt++)
        #pragma unroll
        for (int n8 = 0; n8 < 2; n8++)
            #pragma unroll
            for (int c = 0; c < 4; c++) acc[mt][n8][c] = 0.f;

    int arow[2];
    #pragma unroll
    for (int mt = 0; mt < 2; mt++)
        arow[mt] = wm * 32 + mt * 16 + ((lane >> 3) & 1) * 8 + (lane & 7);
    const int akhi = (lane >> 4) * 8;
    const int brow = wn * 16 + (lane >> 4) * 8 + (lane & 7);
    const int bkhi = ((lane >> 3) & 1) * 8;

    #pragma unroll
    for (int ks = 0; ks < 8; ks++) {
        const int k0 = ks * 16;
        uint32_t ah[2][4], al[2][4], bh[4], bl[4];
        #pragma unroll
        for (int mt = 0; mt < 2; mt++) {
            uint32_t o = swz(arow[mt], (k0 + akhi) * 2);
            ldsm4(aHi + o, ah[mt]);
            ldsm4(aLo + o, al[mt]);
        }
        {
            uint32_t bo = swz(brow, (k0 + bkhi) * 2);
            ldsm4(wHi + bo, bh);
            ldsm4(wLo + bo, bl);
        }
        #pragma unroll
        for (int mt = 0; mt < 2; mt++) {
            mma16816(acc[mt][0], ah[mt], bh[0], bh[1]);
            mma16816(acc[mt][1], ah[mt], bh[2], bh[3]);
        }
        #pragma unroll
        for (int mt = 0; mt < 2; mt++) {
            mma16816(acc[mt][0], al[mt], bh[0], bh[1]);
            mma16816(acc[mt][1], al[mt], bh[2], bh[3]);
        }
        #pragma unroll
        for (int mt = 0; mt < 2; mt++) {
            mma16816(acc[mt][0], ah[mt], bl[0], bl[1]);
            mma16816(acc[mt][1], ah[mt], bl[2], bl[3]);
        }
    }
}

// ================= tensor node kernel (1024 threads, unchanged) =================
#define NOFF_WSH 0
#define NOFF_WSL 32768
#define NOFF_WDH 65536
#define NOFF_WDL 98304
#define NOFF_AHI 131072
#define NOFF_ALO 163840
#define NODE_SMEM_BYTES (196608 + 1024)
#define NTILES_N ((NN + 127) / 128)

__global__ void __launch_bounds__(NTHREADS, 1)
node_mma_kernel(const float* __restrict__ nfeat,
                const float* __restrict__ W_s, const float* __restrict__ W_d)
{
    extern __shared__ char smem_raw[];
    char* ab = (char*)(((uintptr_t)smem_raw + 1023) & ~(uintptr_t)1023);
    const int t = threadIdx.x;
    const int wid = t >> 5, lane = t & 31;
    const int wm = wid & 3, wn = wid >> 2;
    const int quad = lane >> 2, qt = lane & 3;

    const uint32_t u_ahi = smem_u32(ab + NOFF_AHI);
    const uint32_t u_alo = smem_u32(ab + NOFF_ALO);
    const uint32_t u_wsh = smem_u32(ab + NOFF_WSH);
    const uint32_t u_wsl = smem_u32(ab + NOFF_WSL);
    const uint32_t u_wdh = smem_u32(ab + NOFF_WDH);
    const uint32_t u_wdl = smem_u32(ab + NOFF_WDL);

    load_split_matrix(ab + NOFF_WSH, ab + NOFF_WSL, W_s, t, NTHREADS);
    load_split_matrix(ab + NOFF_WDH, ab + NOFF_WDL, W_d, t, NTHREADS);

    for (int tile = blockIdx.x; tile < NTILES_N; tile += gridDim.x) {
        const int n0 = tile * 128;
        __syncthreads();
        for (int p = t; p < DIM * 32; p += NTHREADS) {
            int r = p >> 5, c4 = p & 31;
            int n = n0 + r;
            float4 v = make_float4(0.f, 0.f, 0.f, 0.f);
            if (n < NN) v = reinterpret_cast<const float4*>(nfeat)[(size_t)n * 32 + c4];
            __nv_bfloat16 h0, l0, h1, l1, h2, l2, h3, l3;
            split_bf16(v.x, h0, l0); split_bf16(v.y, h1, l1);
            split_bf16(v.z, h2, l2); split_bf16(v.w, h3, l3);
            uint32_t o = swz(r, c4 * 8);
            *reinterpret_cast<__nv_bfloat162*>(ab + NOFF_AHI + o)     = __nv_bfloat162(h0, h1);
            *reinterpret_cast<__nv_bfloat162*>(ab + NOFF_AHI + o + 4) = __nv_bfloat162(h2, h3);
            *reinterpret_cast<__nv_bfloat162*>(ab + NOFF_ALO + o)     = __nv_bfloat162(l0, l1);
            *reinterpret_cast<__nv_bfloat162*>(ab + NOFF_ALO + o + 4) = __nv_bfloat162(l2, l3);
        }
        __syncthreads();

        float acc[2][2][4];
        warp_gemm_split16(u_ahi, u_alo, u_wsh, u_wsl, wm, wn, lane, acc);
        #pragma unroll
        for (int mt = 0; mt < 2; mt++)
            #pragma unroll
            for (int rh = 0; rh < 2; rh++) {
                int n = n0 + wm * 32 + mt * 16 + quad + rh * 8;
                if (n < NN)
                    #pragma unroll
                    for (int n8 = 0; n8 < 2; n8++) {
                        int col = wn * 16 + n8 * 8 + 2 * qt;
                        *reinterpret_cast<float2*>(&g_sproj[(size_t)n * DIM + col]) =
                            make_float2(acc[mt][n8][rh * 2], acc[mt][n8][rh * 2 + 1]);
                    }
            }

        warp_gemm_split16(u_ahi, u_alo, u_wdh, u_wdl, wm, wn, lane, acc);
        #pragma unroll
        for (int mt = 0; mt < 2; mt++)
            #pragma unroll
            for (int rh = 0; rh < 2; rh++) {
                int n = n0 + wm * 32 + mt * 16 + quad + rh * 8;
                if (n < NN)
                    #pragma unroll
                    for (int n8 = 0; n8 < 2; n8++) {
                        int col = wn * 16 + n8 * 8 + 2 * qt;
                        *reinterpret_cast<float2*>(&g_dproj[(size_t)n * DIM + col]) =
                            make_float2(acc[mt][n8][rh * 2], acc[mt][n8][rh * 2 + 1]);
                    }
            }
    }
}

// ================= mma.sync edge kernel (640 threads, 160-edge tile) =================
#define OFF_W1HI 0
#define OFF_W1LO 32768
#define OFF_W2HI 65536
#define OFF_W2LO 98304
#define OFF_AHI  131072   // 160*256 = 40960
#define OFF_ALO  172032   // 40960
#define OFF_B1   212992
#define OFF_BO   213504
#define OFF_GM   214016
#define OFF_BT   214528
#define OFF_RSUM 215040   // float[4][160] = 2560
#define OFF_RSQ  217600   // 2560
#define OFF_SRC  220160   // int[160]
#define OFF_DST  220800
#define EDGE_SMEM_BYTES (221440 + 1024)

#define NTILES_E (NE / ETM)   // 3750 exactly

__global__ void __launch_bounds__(ETHREADS, 1)
edge_mma_kernel(const float* __restrict__ efeat,
                const int* __restrict__ src, const int* __restrict__ dst,
                const float* __restrict__ W_e, const float* __restrict__ b1,
                const float* __restrict__ W_o, const float* __restrict__ b_o,
                const float* __restrict__ gamma, const float* __restrict__ beta,
                float* __restrict__ out)
{
    extern __shared__ char smem_raw[];
    char* ab = (char*)(((uintptr_t)smem_raw + 1023) & ~(uintptr_t)1023);
    const int t = threadIdx.x;
    const int wid = t >> 5, lane = t & 31;
    const int wm = wid % 5, wn = wid / 5;   // 5(M) x 4(N) warp grid, M32 x N32 tiles

    const uint32_t u_ahi = smem_u32(ab + OFF_AHI);
    const uint32_t u_alo = smem_u32(ab + OFF_ALO);
    const uint32_t u_w1h = smem_u32(ab + OFF_W1HI);
    const uint32_t u_w1l = smem_u32(ab + OFF_W1LO);
    const uint32_t u_w2h = smem_u32(ab + OFF_W2HI);
    const uint32_t u_w2l = smem_u32(ab + OFF_W2LO);

    float* b1s = (float*)(ab + OFF_B1);
    float* bos = (float*)(ab + OFF_BO);
    float* gms = (float*)(ab + OFF_GM);
    float* bts = (float*)(ab + OFF_BT);
    float* rsum = (float*)(ab + OFF_RSUM);
    float* rsq  = (float*)(ab + OFF_RSQ);
    int* srcS = (int*)(ab + OFF_SRC);
    int* dstS = (int*)(ab + OFF_DST);

    load_split_matrix(ab + OFF_W1HI, ab + OFF_W1LO, W_e, t, ETHREADS);
    load_split_matrix(ab + OFF_W2HI, ab + OFF_W2LO, W_o, t, ETHREADS);
    if (t < 128) { b1s[t] = b1[t]; bos[t] = b_o[t]; gms[t] = gamma[t]; bts[t] = beta[t]; }

    const int quad = lane >> 2, qt = lane & 3;

    for (int tile = blockIdx.x; tile < NTILES_E; tile += gridDim.x) {
        const int e0 = tile * ETM;
        __syncthreads();  // previous tile fully consumed

        // ---- load + split efeat tile (exact tiles: no bounds checks)
        for (int p = t; p < ETM * 32; p += ETHREADS) {
            int r = p >> 5, c4 = p & 31;
            float4 v = reinterpret_cast<const float4*>(efeat)[(size_t)(e0 + r) * 32 + c4];
            __nv_bfloat16 h0, l0, h1, l1, h2, l2, h3, l3;
            split_bf16(v.x, h0, l0); split_bf16(v.y, h1, l1);
            split_bf16(v.z, h2, l2); split_bf16(v.w, h3, l3);
            uint32_t o = swz(r, c4 * 8);
            *reinterpret_cast<__nv_bfloat162*>(ab + OFF_AHI + o)     = __nv_bfloat162(h0, h1);
            *reinterpret_cast<__nv_bfloat162*>(ab + OFF_AHI + o + 4) = __nv_bfloat162(h2, h3);
            *reinterpret_cast<__nv_bfloat162*>(ab + OFF_ALO + o)     = __nv_bfloat162(l0, l1);
            *reinterpret_cast<__nv_bfloat162*>(ab + OFF_ALO + o + 4) = __nv_bfloat162(l2, l3);
        }
        if (t < ETM) {
            srcS[t] = src[e0 + t];
            dstS[t] = dst[e0 + t];
        }
        __syncthreads();

        // ---- GEMM1
        float acc[2][4][4];
        warp_gemm_split32(u_ahi, u_alo, u_w1h, u_w1l, wm, wn, lane, acc);
        __syncthreads();  // all warps done reading A before H overwrite

        // ---- epilogue 1: + b1 + gathers, SiLU, split -> H into A buffers
        #pragma unroll
        for (int mt = 0; mt < 2; mt++) {
            #pragma unroll
            for (int rh = 0; rh < 2; rh++) {
                int row = wm * 32 + mt * 16 + quad + rh * 8;
                const float* sp = g_sproj + (size_t)srcS[row] * DIM;
                const float* dp = g_dproj + (size_t)dstS[row] * DIM;
                #pragma unroll
                for (int n8 = 0; n8 < 4; n8++) {
                    int col = wn * 32 + n8 * 8 + 2 * qt;
                    float2 s2 = *reinterpret_cast<const float2*>(&sp[col]);
                    float2 d2 = *reinterpret_cast<const float2*>(&dp[col]);
                    float2 b2 = *reinterpret_cast<const float2*>(&b1s[col]);
                    float x0 = acc[mt][n8][rh * 2 + 0] + b2.x + s2.x + d2.x;
                    float x1 = acc[mt][n8][rh * 2 + 1] + b2.y + s2.y + d2.y;
                    float v0 = x0 / (1.0f + __expf(-x0));
                    float v1 = x1 / (1.0f + __expf(-x1));
                    __nv_bfloat16 h0, l0, h1, l1;
                    split_bf16(v0, h0, l0); split_bf16(v1, h1, l1);
                    uint32_t o = swz(row, col * 2);
                    *reinterpret_cast<__nv_bfloat162*>(ab + OFF_AHI + o) = __nv_bfloat162(h0, h1);
                    *reinterpret_cast<__nv_bfloat162*>(ab + OFF_ALO + o) = __nv_bfloat162(l0, l1);
                }
            }
        }
        __syncthreads();

        // ---- GEMM2
        warp_gemm_split32(u_ahi, u_alo, u_w2h, u_w2l, wm, wn, lane, acc);

        // ---- epilogue 2: + b_o, LayerNorm partials (32-col group per warp)
        #pragma unroll
        for (int mt = 0; mt < 2; mt++) {
            #pragma unroll
            for (int rh = 0; rh < 2; rh++) {
                int row = wm * 32 + mt * 16 + quad + rh * 8;
                float s = 0.f, q = 0.f;
                #pragma unroll
                for (int n8 = 0; n8 < 4; n8++) {
                    int col = wn * 32 + n8 * 8 + 2 * qt;
                    float2 b2 = *reinterpret_cast<const float2*>(&bos[col]);
                    float v0 = acc[mt][n8][rh * 2 + 0] + b2.x;
                    float v1 = acc[mt][n8][rh * 2 + 1] + b2.y;
                    acc[mt][n8][rh * 2 + 0] = v0;
                    acc[mt][n8][rh * 2 + 1] = v1;
                    s += v0 + v1;
                    q += v0 * v0 + v1 * v1;
                }
                s += __shfl_xor_sync(0xffffffffu, s, 1);
                s += __shfl_xor_sync(0xffffffffu, s, 2);
                q += __shfl_xor_sync(0xffffffffu, q, 1);
                q += __shfl_xor_sync(0xffffffffu, q, 2);
                if (qt == 0) {
                    rsum[wn * ETM + row] = s;
                    rsq[wn * ETM + row] = q;
                }
            }
        }
        __syncthreads();

        // ---- normalize + affine + residual + store
        #pragma unroll
        for (int mt = 0; mt < 2; mt++) {
            #pragma unroll
            for (int rh = 0; rh < 2; rh++) {
                int row = wm * 32 + mt * 16 + quad + rh * 8;
                int e = e0 + row;
                float ts = rsum[row] + rsum[ETM + row] + rsum[2 * ETM + row] + rsum[3 * ETM + row];
                float tq = rsq[row] + rsq[ETM + row] + rsq[2 * ETM + row] + rsq[3 * ETM + row];
                float mean = ts * (1.0f / 128.0f);
                float var = tq * (1.0f / 128.0f) - mean * mean;
                float rstd = rsqrtf(var + 1e-5f);
                #pragma unroll
                for (int n8 = 0; n8 < 4; n8++) {
                    int col = wn * 32 + n8 * 8 + 2 * qt;
                    float2 g2 = *reinterpret_cast<const float2*>(&gms[col]);
                    float2 t2 = *reinterpret_cast<const float2*>(&bts[col]);
                    float2 r2 = *reinterpret_cast<const float2*>(&efeat[(size_t)e * DIM + col]);
                    float o0 = (acc[mt][n8][rh * 2 + 0] - mean) * rstd * g2.x + t2.x + r2.x;
                    float o1 = (acc[mt][n8][rh * 2 + 1] - mean) * rstd * g2.y + t2.y + r2.y;
                    *reinterpret_cast<float2*>(&out[(size_t)e * DIM + col]) = make_float2(o0, o1);
                }
            }
        }
    }
}

extern "C" void kernel_launch(void* const* d_in, const int* in_sizes, int n_in,
                              void* d_out, int out_size) {
    const float* efeat = (const float*)d_in[0];
    const float* nfeat = (const float*)d_in[1];
    const int*   src   = (const int*)d_in[2];
    const int*   dst   = (const int*)d_in[3];
    const float* W_e   = (const float*)d_in[4];
    const float* W_s   = (const float*)d_in[5];
    const float* W_d   = (const float*)d_in[6];
    const float* b1    = (const float*)d_in[7];
    const float* W_o   = (const float*)d_in[8];
    const float* b_o   = (const float*)d_in[9];
    const float* gamma = (const float*)d_in[10];
    const float* beta  = (const float*)d_in[11];
    float* out = (float*)d_out;

    cudaFuncSetAttribute(node_mma_kernel, cudaFuncAttributeMaxDynamicSharedMemorySize,
                         NODE_SMEM_BYTES);
    cudaFuncSetAttribute(edge_mma_kernel, cudaFuncAttributeMaxDynamicSharedMemorySize,
                         EDGE_SMEM_BYTES);

    node_mma_kernel<<<NSM, NTHREADS, NODE_SMEM_BYTES>>>(nfeat, W_s, W_d);
    edge_mma_kernel<<<NSM, ETHREADS, EDGE_SMEM_BYTES>>>(efeat, src, dst, W_e, b1, W_o, b_o,
                                                        gamma, beta, out);
    cudaMemcpyAsync(out + (size_t)NE * DIM, nfeat,
                    (size_t)NN * DIM * sizeof(float), cudaMemcpyDeviceToDevice);
}

// round 12
// speedup vs baseline: 2.3442x; 1.3007x over previous
#include <cuda_runtime.h>
#include <cuda_fp16.h>
#include <cstdint>

#define NE 600000
#define NN 50000
#define DIM 128
#define NTHREADS 1024
#define ETHREADS 512
#define ETM 128
#define NSM 152

// Scratch for node projections
__device__ float g_sproj[(size_t)NN * DIM];
__device__ float g_dproj[(size_t)NN * DIM];

// ---------------- common helpers ----------------
__device__ __forceinline__ uint32_t smem_u32(const void* p) {
    uint32_t a;
    asm("{ .reg .u64 t; cvta.to.shared.u64 t, %1; cvt.u32.u64 %0, t; }" : "=r"(a) : "l"(p));
    return a;
}

// Swizzled tile layout: rows x 128 fp16, row stride 256B.
// 16B chunk index c (0..15) -> (c&8) | ((c ^ r) & 7): ldmatrix conflict-free.
__device__ __forceinline__ uint32_t swz(int r, int kb) {
    int chunk = kb >> 4;
    int c2 = (chunk & 8) | ((chunk ^ r) & 7);
    return (uint32_t)(r * 256 + c2 * 16 + (kb & 15));
}

// load 128x128 fp32 row-major matrix, convert to fp16 swizzled tile
__device__ __forceinline__ void load_matrix_f16(char* dstB, const float* __restrict__ W,
                                                int t, int nthr) {
    for (int p = t; p < DIM * (DIM / 4); p += nthr) {
        int r = p >> 5, c4 = p & 31;
        float4 v = reinterpret_cast<const float4*>(W)[p];
        __half2 p0 = __floats2half2_rn(v.x, v.y);
        __half2 p1 = __floats2half2_rn(v.z, v.w);
        uint32_t o = swz(r, c4 * 8);
        *reinterpret_cast<__half2*>(dstB + o)     = p0;
        *reinterpret_cast<__half2*>(dstB + o + 4) = p1;
    }
}

__device__ __forceinline__ void ldsm4(uint32_t addr, uint32_t r[4]) {
    asm volatile("ldmatrix.sync.aligned.m8n8.x4.shared.b16 {%0,%1,%2,%3}, [%4];"
                 : "=r"(r[0]), "=r"(r[1]), "=r"(r[2]), "=r"(r[3]) : "r"(addr));
}
__device__ __forceinline__ void mma16816(float c[4], const uint32_t a[4],
                                         uint32_t b0, uint32_t b1) {
    asm volatile("mma.sync.aligned.m16n8k16.row.col.f32.f16.f16.f32 "
                 "{%0,%1,%2,%3}, {%4,%5,%6,%7}, {%8,%9}, {%0,%1,%2,%3};"
                 : "+f"(c[0]), "+f"(c[1]), "+f"(c[2]), "+f"(c[3])
                 : "r"(a[0]), "r"(a[1]), "r"(a[2]), "r"(a[3]), "r"(b0), "r"(b1));
}

// Warp GEMM: D(M32xN32) = A(M32xK128) * W^T(K128xN32), single fp16 term.
// 8 independent accumulators per k-step for ILP.
__device__ __forceinline__ void warp_gemm_f16_n32(
    uint32_t aB, uint32_t wB, int wm, int wn, int lane, float acc[2][4][4])
{
    #pragma unroll
    for (int mt = 0; mt < 2; mt++)
        #pragma unroll
        for (int n8 = 0; n8 < 4; n8++)
            #pragma unroll
            for (int c = 0; c < 4; c++) acc[mt][n8][c] = 0.f;

    int arow[2];
    #pragma unroll
    for (int mt = 0; mt < 2; mt++)
        arow[mt] = wm * 32 + mt * 16 + ((lane >> 3) & 1) * 8 + (lane & 7);
    const int akhi = (lane >> 4) * 8;
    int brow[2];
    #pragma unroll
    for (int np = 0; np < 2; np++)
        brow[np] = wn * 32 + np * 16 + (lane >> 4) * 8 + (lane & 7);
    const int bkhi = ((lane >> 3) & 1) * 8;

    #pragma unroll
    for (int ks = 0; ks < 8; ks++) {
        const int k0 = ks * 16;
        uint32_t a[2][4], b[2][4];
        #pragma unroll
        for (int mt = 0; mt < 2; mt++)
            ldsm4(aB + swz(arow[mt], (k0 + akhi) * 2), a[mt]);
        #pragma unroll
        for (int np = 0; np < 2; np++)
            ldsm4(wB + swz(brow[np], (k0 + bkhi) * 2), b[np]);
        #pragma unroll
        for (int np = 0; np < 2; np++)
            #pragma unroll
            for (int mt = 0; mt < 2; mt++) {
                mma16816(acc[mt][2 * np],     a[mt], b[np][0], b[np][1]);
                mma16816(acc[mt][2 * np + 1], a[mt], b[np][2], b[np][3]);
            }
    }
}

// Warp GEMM: D(M32xN16), node kernel (4x8 warp grid, 1024 threads).
__device__ __forceinline__ void warp_gemm_f16_n16(
    uint32_t aB, uint32_t wB, int wm, int wn, int lane, float acc[2][2][4])
{
    #pragma unroll
    for (int mt = 0; mt < 2; mt++)
        #pragma unroll
        for (int n8 = 0; n8 < 2; n8++)
            #pragma unroll
            for (int c = 0; c < 4; c++) acc[mt][n8][c] = 0.f;

    int arow[2];
    #pragma unroll
    for (int mt = 0; mt < 2; mt++)
        arow[mt] = wm * 32 + mt * 16 + ((lane >> 3) & 1) * 8 + (lane & 7);
    const int akhi = (lane >> 4) * 8;
    const int brow = wn * 16 + (lane >> 4) * 8 + (lane & 7);
    const int bkhi = ((lane >> 3) & 1) * 8;

    #pragma unroll
    for (int ks = 0; ks < 8; ks++) {
        const int k0 = ks * 16;
        uint32_t a[2][4], b[4];
        #pragma unroll
        for (int mt = 0; mt < 2; mt++)
            ldsm4(aB + swz(arow[mt], (k0 + akhi) * 2), a[mt]);
        ldsm4(wB + swz(brow, (k0 + bkhi) * 2), b);
        #pragma unroll
        for (int mt = 0; mt < 2; mt++) {
            mma16816(acc[mt][0], a[mt], b[0], b[1]);
            mma16816(acc[mt][1], a[mt], b[2], b[3]);
        }
    }
}

// ================= tensor node kernel (fp16 single-term) =================
#define NOFF_WS 0
#define NOFF_WD 32768
#define NOFF_A  65536
#define NODE_SMEM_BYTES (98304 + 1024)
#define NTILES_N ((NN + 127) / 128)

__global__ void __launch_bounds__(NTHREADS, 1)
node_mma_kernel(const float* __restrict__ nfeat,
                const float* __restrict__ W_s, const float* __restrict__ W_d)
{
    extern __shared__ char smem_raw[];
    char* ab = (char*)(((uintptr_t)smem_raw + 1023) & ~(uintptr_t)1023);
    const int t = threadIdx.x;
    const int wid = t >> 5, lane = t & 31;
    const int wm = wid & 3, wn = wid >> 2;
    const int quad = lane >> 2, qt = lane & 3;

    const uint32_t u_a  = smem_u32(ab + NOFF_A);
    const uint32_t u_ws = smem_u32(ab + NOFF_WS);
    const uint32_t u_wd = smem_u32(ab + NOFF_WD);

    load_matrix_f16(ab + NOFF_WS, W_s, t, NTHREADS);
    load_matrix_f16(ab + NOFF_WD, W_d, t, NTHREADS);

    for (int tile = blockIdx.x; tile < NTILES_N; tile += gridDim.x) {
        const int n0 = tile * 128;
        __syncthreads();
        for (int p = t; p < DIM * 32; p += NTHREADS) {
            int r = p >> 5, c4 = p & 31;
            int n = n0 + r;
            float4 v = make_float4(0.f, 0.f, 0.f, 0.f);
            if (n < NN) v = reinterpret_cast<const float4*>(nfeat)[(size_t)n * 32 + c4];
            uint32_t o = swz(r, c4 * 8);
            *reinterpret_cast<__half2*>(ab + NOFF_A + o)     = __floats2half2_rn(v.x, v.y);
            *reinterpret_cast<__half2*>(ab + NOFF_A + o + 4) = __floats2half2_rn(v.z, v.w);
        }
        __syncthreads();

        float acc[2][2][4];
        warp_gemm_f16_n16(u_a, u_ws, wm, wn, lane, acc);
        #pragma unroll
        for (int mt = 0; mt < 2; mt++)
            #pragma unroll
            for (int rh = 0; rh < 2; rh++) {
                int n = n0 + wm * 32 + mt * 16 + quad + rh * 8;
                if (n < NN)
                    #pragma unroll
                    for (int n8 = 0; n8 < 2; n8++) {
                        int col = wn * 16 + n8 * 8 + 2 * qt;
                        *reinterpret_cast<float2*>(&g_sproj[(size_t)n * DIM + col]) =
                            make_float2(acc[mt][n8][rh * 2], acc[mt][n8][rh * 2 + 1]);
                    }
            }

        warp_gemm_f16_n16(u_a, u_wd, wm, wn, lane, acc);
        #pragma unroll
        for (int mt = 0; mt < 2; mt++)
            #pragma unroll
            for (int rh = 0; rh < 2; rh++) {
                int n = n0 + wm * 32 + mt * 16 + quad + rh * 8;
                if (n < NN)
                    #pragma unroll
                    for (int n8 = 0; n8 < 2; n8++) {
                        int col = wn * 16 + n8 * 8 + 2 * qt;
                        *reinterpret_cast<float2*>(&g_dproj[(size_t)n * DIM + col]) =
                            make_float2(acc[mt][n8][rh * 2], acc[mt][n8][rh * 2 + 1]);
                    }
            }
    }
}

// ====== mma.sync edge kernel (fp16 single-term, 512 threads, 2 CTAs/SM) ======
#define OFF_W1   0
#define OFF_W2   32768
#define OFF_A    65536    // 128*256 = 32768
#define OFF_B1   98304
#define OFF_BO   98816
#define OFF_GM   99328
#define OFF_BT   99840
#define OFF_RSUM 100352   // float[4][128] = 2048
#define OFF_RSQ  102400   // 2048
#define OFF_SRC  104448   // int[128]
#define OFF_DST  104960
#define EDGE_SMEM_BYTES (105472 + 1024)

#define NTILES_E ((NE + ETM - 1) / ETM)   // 4688

__global__ void __launch_bounds__(ETHREADS, 2)
edge_mma_kernel(const float* __restrict__ efeat,
                const int* __restrict__ src, const int* __restrict__ dst,
                const float* __restrict__ W_e, const float* __restrict__ b1,
                const float* __restrict__ W_o, const float* __restrict__ b_o,
                const float* __restrict__ gamma, const float* __restrict__ beta,
                float* __restrict__ out)
{
    extern __shared__ char smem_raw[];
    char* ab = (char*)(((uintptr_t)smem_raw + 1023) & ~(uintptr_t)1023);
    const int t = threadIdx.x;
    const int wid = t >> 5, lane = t & 31;
    const int wm = wid & 3, wn = wid >> 2;   // 4(M) x 4(N) warp grid, M32 x N32 tiles

    const uint32_t u_a  = smem_u32(ab + OFF_A);
    const uint32_t u_w1 = smem_u32(ab + OFF_W1);
    const uint32_t u_w2 = smem_u32(ab + OFF_W2);

    float* b1s = (float*)(ab + OFF_B1);
    float* bos = (float*)(ab + OFF_BO);
    float* gms = (float*)(ab + OFF_GM);
    float* bts = (float*)(ab + OFF_BT);
    float* rsum = (float*)(ab + OFF_RSUM);
    float* rsq  = (float*)(ab + OFF_RSQ);
    int* srcS = (int*)(ab + OFF_SRC);
    int* dstS = (int*)(ab + OFF_DST);

    load_matrix_f16(ab + OFF_W1, W_e, t, ETHREADS);
    load_matrix_f16(ab + OFF_W2, W_o, t, ETHREADS);
    if (t < 128) { b1s[t] = b1[t]; bos[t] = b_o[t]; gms[t] = gamma[t]; bts[t] = beta[t]; }

    const int quad = lane >> 2, qt = lane & 3;

    for (int tile = blockIdx.x; tile < NTILES_E; tile += gridDim.x) {
        const int e0 = tile * ETM;
        __syncthreads();  // previous tile fully consumed

        // ---- load + convert efeat tile; load indices
        for (int p = t; p < ETM * 32; p += ETHREADS) {
            int r = p >> 5, c4 = p & 31;
            int e = e0 + r;
            float4 v = make_float4(0.f, 0.f, 0.f, 0.f);
            if (e < NE) v = reinterpret_cast<const float4*>(efeat)[(size_t)e * 32 + c4];
            uint32_t o = swz(r, c4 * 8);
            *reinterpret_cast<__half2*>(ab + OFF_A + o)     = __floats2half2_rn(v.x, v.y);
            *reinterpret_cast<__half2*>(ab + OFF_A + o + 4) = __floats2half2_rn(v.z, v.w);
        }
        if (t < ETM) {
            int e = e0 + t;
            srcS[t] = (e < NE) ? src[e] : 0;
            dstS[t] = (e < NE) ? dst[e] : 0;
        }
        __syncthreads();

        // ---- GEMM1
        float acc[2][4][4];
        warp_gemm_f16_n32(u_a, u_w1, wm, wn, lane, acc);
        __syncthreads();  // all warps done reading A before H overwrite

        // ---- epilogue 1: + b1 + gathers, SiLU, convert -> H into A buffer
        #pragma unroll
        for (int mt = 0; mt < 2; mt++) {
            #pragma unroll
            for (int rh = 0; rh < 2; rh++) {
                int row = wm * 32 + mt * 16 + quad + rh * 8;
                const float* sp = g_sproj + (size_t)srcS[row] * DIM;
                const float* dp = g_dproj + (size_t)dstS[row] * DIM;
                #pragma unroll
                for (int n8 = 0; n8 < 4; n8++) {
                    int col = wn * 32 + n8 * 8 + 2 * qt;
                    float2 s2 = *reinterpret_cast<const float2*>(&sp[col]);
                    float2 d2 = *reinterpret_cast<const float2*>(&dp[col]);
                    float2 b2 = *reinterpret_cast<const float2*>(&b1s[col]);
                    float x0 = acc[mt][n8][rh * 2 + 0] + b2.x + s2.x + d2.x;
                    float x1 = acc[mt][n8][rh * 2 + 1] + b2.y + s2.y + d2.y;
                    float v0 = x0 / (1.0f + __expf(-x0));
                    float v1 = x1 / (1.0f + __expf(-x1));
                    *reinterpret_cast<__half2*>(ab + OFF_A + swz(row, col * 2)) =
                        __floats2half2_rn(v0, v1);
                }
            }
        }
        __syncthreads();

        // ---- GEMM2
        warp_gemm_f16_n32(u_a, u_w2, wm, wn, lane, acc);

        // ---- epilogue 2: + b_o, LayerNorm partials (32-col group per warp)
        #pragma unroll
        for (int mt = 0; mt < 2; mt++) {
            #pragma unroll
            for (int rh = 0; rh < 2; rh++) {
                int row = wm * 32 + mt * 16 + quad + rh * 8;
                float s = 0.f, q = 0.f;
                #pragma unroll
                for (int n8 = 0; n8 < 4; n8++) {
                    int col = wn * 32 + n8 * 8 + 2 * qt;
                    float2 b2 = *reinterpret_cast<const float2*>(&bos[col]);
                    float v0 = acc[mt][n8][rh * 2 + 0] + b2.x;
                    float v1 = acc[mt][n8][rh * 2 + 1] + b2.y;
                    acc[mt][n8][rh * 2 + 0] = v0;
                    acc[mt][n8][rh * 2 + 1] = v1;
                    s += v0 + v1;
                    q += v0 * v0 + v1 * v1;
                }
                s += __shfl_xor_sync(0xffffffffu, s, 1);
                s += __shfl_xor_sync(0xffffffffu, s, 2);
                q += __shfl_xor_sync(0xffffffffu, q, 1);
                q += __shfl_xor_sync(0xffffffffu, q, 2);
                if (qt == 0) {
                    rsum[wn * ETM + row] = s;
                    rsq[wn * ETM + row] = q;
                }
            }
        }
        __syncthreads();

        // ---- normalize + affine + residual + store
        #pragma unroll
        for (int mt = 0; mt < 2; mt++) {
            #pragma unroll
            for (int rh = 0; rh < 2; rh++) {
                int row = wm * 32 + mt * 16 + quad + rh * 8;
                int e = e0 + row;
                if (e >= NE) continue;
                float ts = rsum[row] + rsum[ETM + row] + rsum[2 * ETM + row] + rsum[3 * ETM + row];
                float tq = rsq[row] + rsq[ETM + row] + rsq[2 * ETM + row] + rsq[3 * ETM + row];
                float mean = ts * (1.0f / 128.0f);
                float var = tq * (1.0f / 128.0f) - mean * mean;
                float rstd = rsqrtf(var + 1e-5f);
                #pragma unroll
                for (int n8 = 0; n8 < 4; n8++) {
                    int col = wn * 32 + n8 * 8 + 2 * qt;
                    float2 g2 = *reinterpret_cast<const float2*>(&gms[col]);
                    float2 t2 = *reinterpret_cast<const float2*>(&bts[col]);
                    float2 r2 = *reinterpret_cast<const float2*>(&efeat[(size_t)e * DIM + col]);
                    float o0 = (acc[mt][n8][rh * 2 + 0] - mean) * rstd * g2.x + t2.x + r2.x;
                    float o1 = (acc[mt][n8][rh * 2 + 1] - mean) * rstd * g2.y + t2.y + r2.y;
                    *reinterpret_cast<float2*>(&out[(size_t)e * DIM + col]) = make_float2(o0, o1);
                }
            }
        }
    }
}

extern "C" void kernel_launch(void* const* d_in, const int* in_sizes, int n_in,
                              void* d_out, int out_size) {
    const float* efeat = (const float*)d_in[0];
    const float* nfeat = (const float*)d_in[1];
    const int*   src   = (const int*)d_in[2];
    const int*   dst   = (const int*)d_in[3];
    const float* W_e   = (const float*)d_in[4];
    const float* W_s   = (const float*)d_in[5];
    const float* W_d   = (const float*)d_in[6];
    const float* b1    = (const float*)d_in[7];
    const float* W_o   = (const float*)d_in[8];
    const float* b_o   = (const float*)d_in[9];
    const float* gamma = (const float*)d_in[10];
    const float* beta  = (const float*)d_in[11];
    float* out = (float*)d_out;

    cudaFuncSetAttribute(node_mma_kernel, cudaFuncAttributeMaxDynamicSharedMemorySize,
                         NODE_SMEM_BYTES);
    cudaFuncSetAttribute(edge_mma_kernel, cudaFuncAttributeMaxDynamicSharedMemorySize,
                         EDGE_SMEM_BYTES);

    node_mma_kernel<<<NSM, NTHREADS, NODE_SMEM_BYTES>>>(nfeat, W_s, W_d);
    edge_mma_kernel<<<NSM * 2, ETHREADS, EDGE_SMEM_BYTES>>>(efeat, src, dst, W_e, b1,
                                                            W_o, b_o, gamma, beta, out);
    cudaMemcpyAsync(out + (size_t)NE * DIM, nfeat,
                    (size_t)NN * DIM * sizeof(float), cudaMemcpyDeviceToDevice);
}